// round 1
// baseline (speedup 1.0000x reference)
#include <cuda_runtime.h>

// ---------------------------------------------------------------------------
// CrossAttention: B=8, LA=LB=2048, D=H=512, fp32 throughout.
//   mapped_a = input_a @ Wa + ba ; mapped_b = input_b @ Wb + bb
//   S = scale * mapped_a @ mapped_b^T ; masked -> -1e9
//   att_a  = softmax(S, axis=-1)  (row softmax, over j)
//   att_bT = softmax(S, axis=1)   (col softmax, over i)
//   output_a = att_bT @ input_b + input_a
//   output_b = att_a^T @ input_a + input_b
// ---------------------------------------------------------------------------

namespace {
constexpr int NB  = 8;
constexpr int NLA = 2048;
constexpr int NLB = 2048;
constexpr int ND  = 512;
constexpr int NH  = 512;
constexpr float SCALE = 0.04419417382415922f; // 1/sqrt(512)

constexpr int BM = 128, BN = 128, BK = 8;
constexpr int LDS = 132;                      // padded smem stride (multiple of 4)
}

// Scratch (static __device__ globals: allocation-guard safe)
__device__ float g_ma[NB * NLA * NH];
__device__ float g_mb[NB * NLB * NH];
__device__ float g_s[(size_t)NB * NLA * NLB];
__device__ float g_rmax[NB * NLA];
__device__ float g_rinv[NB * NLA];
__device__ float g_cmax[NB * NLB];
__device__ float g_cinv[NB * NLB];

// ---------------------------------------------------------------------------
// Generic 128x128x8 SGEMM, 256 threads, 8x8 microtile.
// MODE 0: C[16384,512] = X0[16384,512] @ X1[512,512] + X2(bias); C = WHICH?g_mb:g_ma
// MODE 1: per batch z: S = scale * g_ma @ g_mb^T, mask -> -1e9
// MODE 2: per batch z: OUT_a = exp(S - cmax[j])*cinv[j] @ X0(input_b) + X2(input_a)
// MODE 3: per batch z: OUT_b = (exp(S - rmax[i])*rinv[i])^T @ X0(input_a) + X2(input_b)
// ---------------------------------------------------------------------------
template <int MODE, int WHICH>
__global__ void __launch_bounds__(256)
gemm_k(const float* __restrict__ X0, const float* __restrict__ X1,
       const float* __restrict__ X2,
       const int* __restrict__ MAv, const int* __restrict__ MBv,
       float* __restrict__ OUT)
{
    constexpr int K   = (MODE <= 1) ? 512 : 2048;
    constexpr int LDA = (MODE >= 2) ? 2048 : 512;
    constexpr int LDC = (MODE == 1) ? 2048 : 512;

    const int z  = blockIdx.z;
    const int m0 = blockIdx.y * BM;
    const int n0 = blockIdx.x * BN;
    const int t  = threadIdx.x;

    __shared__ __align__(16) float As[BK][LDS];
    __shared__ __align__(16) float Bs[BK][LDS];

    const float* Ap = nullptr;
    const float* Bp = nullptr;
    float*       Cp = nullptr;
    const float* pmax = nullptr;
    const float* pinv = nullptr;
    const float* epi  = nullptr;

    if (MODE == 0) {
        Ap = X0; Bp = X1; Cp = WHICH ? g_mb : g_ma; epi = X2;
    } else if (MODE == 1) {
        Ap = g_ma + (size_t)z * NLA * NH;
        Bp = g_mb + (size_t)z * NLB * NH;
        Cp = g_s  + (size_t)z * NLA * NLB;
    } else if (MODE == 2) {
        Ap = g_s + (size_t)z * NLA * NLB;
        Bp = X0  + (size_t)z * NLB * ND;
        Cp = OUT + (size_t)z * NLA * ND;
        epi  = X2 + (size_t)z * NLA * ND;
        pmax = g_cmax + z * NLB;
        pinv = g_cinv + z * NLB;
    } else {
        Ap = g_s + (size_t)z * NLA * NLB;
        Bp = X0  + (size_t)z * NLA * ND;
        Cp = OUT + (size_t)z * NLB * ND;
        epi  = X2 + (size_t)z * NLB * ND;
        pmax = g_rmax + z * NLA;
        pinv = g_rinv + z * NLA;
    }

    const int a_r = t >> 1;          // 0..127
    const int a_c = (t & 1) * 4;     // 0 or 4
    const int l_k = t >> 5;          // 0..7
    const int l_n = (t & 31) * 4;    // 0..124
    const int tm  = (t >> 4) * 8;
    const int tn  = (t & 15) * 8;

    float acc[8][8] = {};

    for (int kt = 0; kt < K; kt += BK) {
        // ---- load A tile into As[k][m] ----
        if (MODE == 3) {
            // A' = S^T with per-row(=k) softmax transform, coalesced along m
            float4 v = *(const float4*)(Ap + (size_t)(kt + l_k) * NLB + m0 + l_n);
            float mx = pmax[kt + l_k], iv = pinv[kt + l_k];
            v.x = __expf(v.x - mx) * iv;
            v.y = __expf(v.y - mx) * iv;
            v.z = __expf(v.z - mx) * iv;
            v.w = __expf(v.w - mx) * iv;
            *(float4*)&As[l_k][l_n] = v;
        } else {
            float4 v = *(const float4*)(Ap + (size_t)(m0 + a_r) * LDA + kt + a_c);
            if (MODE == 2) {
                float4 mx = *(const float4*)(pmax + kt + a_c);
                float4 iv = *(const float4*)(pinv + kt + a_c);
                v.x = __expf(v.x - mx.x) * iv.x;
                v.y = __expf(v.y - mx.y) * iv.y;
                v.z = __expf(v.z - mx.z) * iv.z;
                v.w = __expf(v.w - mx.w) * iv.w;
            }
            As[a_c + 0][a_r] = v.x;
            As[a_c + 1][a_r] = v.y;
            As[a_c + 2][a_r] = v.z;
            As[a_c + 3][a_r] = v.w;
        }
        // ---- load B tile into Bs[k][n] ----
        if (MODE == 1) {
            // B used transposed: Bs[k][n] = mapped_b[n][k]
            float4 v = *(const float4*)(Bp + (size_t)(n0 + a_r) * NH + kt + a_c);
            Bs[a_c + 0][a_r] = v.x;
            Bs[a_c + 1][a_r] = v.y;
            Bs[a_c + 2][a_r] = v.z;
            Bs[a_c + 3][a_r] = v.w;
        } else {
            float4 v = *(const float4*)(Bp + (size_t)(kt + l_k) * 512 + n0 + l_n);
            *(float4*)&Bs[l_k][l_n] = v;
        }
        __syncthreads();

        // ---- 8x8 microtile FMA ----
        #pragma unroll
        for (int k = 0; k < BK; ++k) {
            float4 a0 = *(const float4*)&As[k][tm];
            float4 a1 = *(const float4*)&As[k][tm + 4];
            float4 b0 = *(const float4*)&Bs[k][tn];
            float4 b1 = *(const float4*)&Bs[k][tn + 4];
            float ar[8] = {a0.x, a0.y, a0.z, a0.w, a1.x, a1.y, a1.z, a1.w};
            float br[8] = {b0.x, b0.y, b0.z, b0.w, b1.x, b1.y, b1.z, b1.w};
            #pragma unroll
            for (int i = 0; i < 8; ++i)
                #pragma unroll
                for (int j = 0; j < 8; ++j)
                    acc[i][j] = fmaf(ar[i], br[j], acc[i][j]);
        }
        __syncthreads();
    }

    // ---- epilogue ----
    if (MODE == 1) {
        int mb8[8];
        #pragma unroll
        for (int j = 0; j < 8; ++j) mb8[j] = MBv[z * NLB + n0 + tn + j];
        #pragma unroll
        for (int i = 0; i < 8; ++i) {
            const int row = m0 + tm + i;
            const int mav = MAv[z * NLA + row];
            #pragma unroll
            for (int j4 = 0; j4 < 8; j4 += 4) {
                float4 o;
                o.x = (mav * mb8[j4 + 0] == 0) ? -1e9f : acc[i][j4 + 0] * SCALE;
                o.y = (mav * mb8[j4 + 1] == 0) ? -1e9f : acc[i][j4 + 1] * SCALE;
                o.z = (mav * mb8[j4 + 2] == 0) ? -1e9f : acc[i][j4 + 2] * SCALE;
                o.w = (mav * mb8[j4 + 3] == 0) ? -1e9f : acc[i][j4 + 3] * SCALE;
                *(float4*)(Cp + (size_t)row * LDC + n0 + tn + j4) = o;
            }
        }
    } else if (MODE == 0) {
        float4 b0 = *(const float4*)(epi + n0 + tn);
        float4 b1 = *(const float4*)(epi + n0 + tn + 4);
        const float bv[8] = {b0.x, b0.y, b0.z, b0.w, b1.x, b1.y, b1.z, b1.w};
        #pragma unroll
        for (int i = 0; i < 8; ++i) {
            const int row = m0 + tm + i;
            #pragma unroll
            for (int j4 = 0; j4 < 8; j4 += 4) {
                float4 o;
                o.x = acc[i][j4 + 0] + bv[j4 + 0];
                o.y = acc[i][j4 + 1] + bv[j4 + 1];
                o.z = acc[i][j4 + 2] + bv[j4 + 2];
                o.w = acc[i][j4 + 3] + bv[j4 + 3];
                *(float4*)(Cp + (size_t)row * LDC + n0 + tn + j4) = o;
            }
        }
    } else {
        #pragma unroll
        for (int i = 0; i < 8; ++i) {
            const int row = m0 + tm + i;
            #pragma unroll
            for (int j4 = 0; j4 < 8; j4 += 4) {
                float4 e = *(const float4*)(epi + (size_t)row * ND + n0 + tn + j4);
                float4 o;
                o.x = acc[i][j4 + 0] + e.x;
                o.y = acc[i][j4 + 1] + e.y;
                o.z = acc[i][j4 + 2] + e.z;
                o.w = acc[i][j4 + 3] + e.w;
                *(float4*)(Cp + (size_t)row * ND + n0 + tn + j4) = o;
            }
        }
    }
}

// ---------------------------------------------------------------------------
// Row softmax stats (over j / axis -1): one warp per row, online (max, sum).
// ---------------------------------------------------------------------------
__global__ void __launch_bounds__(256) rowstats_k()
{
    const int warp = threadIdx.x >> 5;
    const int lane = threadIdx.x & 31;
    const int row  = blockIdx.x * 8 + warp;          // [0, NB*NLA)
    const float* p = g_s + (size_t)row * NLB;

    float m = -1e30f, l = 0.f;
    for (int c = lane * 4; c < NLB; c += 128) {
        float4 v = *(const float4*)(p + c);
        float mv = fmaxf(fmaxf(v.x, v.y), fmaxf(v.z, v.w));
        float nm = fmaxf(m, mv);
        l = l * __expf(m - nm)
          + __expf(v.x - nm) + __expf(v.y - nm)
          + __expf(v.z - nm) + __expf(v.w - nm);
        m = nm;
    }
    #pragma unroll
    for (int o = 16; o; o >>= 1) {
        float om = __shfl_xor_sync(0xffffffffu, m, o);
        float ol = __shfl_xor_sync(0xffffffffu, l, o);
        float nm = fmaxf(m, om);
        l = l * __expf(m - nm) + ol * __expf(om - nm);
        m = nm;
    }
    if (lane == 0) {
        g_rmax[row] = m;
        g_rinv[row] = 1.f / l;
    }
}

// ---------------------------------------------------------------------------
// Column softmax stats (over i / axis 1): one thread per column, coalesced
// row sweep, two independent online chains for latency.
// ---------------------------------------------------------------------------
__global__ void __launch_bounds__(256) colstats_k()
{
    const int z = blockIdx.y;
    const int j = blockIdx.x * 256 + threadIdx.x;
    const float* p = g_s + (size_t)z * NLA * NLB + j;

    float m0 = -1e30f, l0 = 0.f, m1 = -1e30f, l1 = 0.f;
    for (int i = 0; i < NLA; i += 2) {
        float v0 = p[(size_t)i * NLB];
        float v1 = p[(size_t)(i + 1) * NLB];
        float n0 = fmaxf(m0, v0);
        l0 = l0 * __expf(m0 - n0) + __expf(v0 - n0);
        m0 = n0;
        float n1 = fmaxf(m1, v1);
        l1 = l1 * __expf(m1 - n1) + __expf(v1 - n1);
        m1 = n1;
    }
    float nm = fmaxf(m0, m1);
    float l  = l0 * __expf(m0 - nm) + l1 * __expf(m1 - nm);
    g_cmax[z * NLB + j] = nm;
    g_cinv[z * NLB + j] = 1.f / l;
}

// ---------------------------------------------------------------------------
extern "C" void kernel_launch(void* const* d_in, const int* in_sizes, int n_in,
                              void* d_out, int out_size)
{
    (void)in_sizes; (void)n_in; (void)out_size;
    const float* input_a = (const float*)d_in[0];
    const float* input_b = (const float*)d_in[1];
    const int*   mask_a  = (const int*)d_in[2];
    const int*   mask_b  = (const int*)d_in[3];
    const float* Wa      = (const float*)d_in[4];
    const float* ba      = (const float*)d_in[5];
    const float* Wb      = (const float*)d_in[6];
    const float* bb      = (const float*)d_in[7];
    float* out = (float*)d_out;

    // 1) projections
    gemm_k<0, 0><<<dim3(NH / BN, (NB * NLA) / BM, 1), 256>>>(
        input_a, Wa, ba, nullptr, nullptr, nullptr);
    gemm_k<0, 1><<<dim3(NH / BN, (NB * NLB) / BM, 1), 256>>>(
        input_b, Wb, bb, nullptr, nullptr, nullptr);

    // 2) masked scores
    gemm_k<1, 0><<<dim3(NLB / BN, NLA / BM, NB), 256>>>(
        nullptr, nullptr, nullptr, mask_a, mask_b, nullptr);

    // 3) softmax stats
    rowstats_k<<<(NB * NLA) / 8, 256>>>();
    colstats_k<<<dim3(NLB / 256, NB), 256>>>();

    // 4) attention-weighted outputs + residual
    gemm_k<2, 0><<<dim3(ND / BN, NLA / BM, NB), 256>>>(
        input_b, nullptr, input_a, nullptr, nullptr, out);
    gemm_k<3, 0><<<dim3(ND / BN, NLB / BM, NB), 256>>>(
        input_a, nullptr, input_b, nullptr, nullptr,
        out + (size_t)NB * NLA * ND);
}

// round 3
// speedup vs baseline: 1.9595x; 1.9595x over previous
#include <cuda_runtime.h>
#include <cstdint>

// ---------------------------------------------------------------------------
// CrossAttention via mma.sync tf32 (HMMA fallback; tcgen05 unavailable because
// the harness compiles at virtual arch compute_103 without the 'a' feature).
// ---------------------------------------------------------------------------

namespace {
constexpr int NB = 8, NLA = 2048, NLB = 2048, ND = 512, NH = 512;
constexpr float SCALE = 0.04419417382415922f; // 1/sqrt(512)

constexpr int BM = 128, BN = 128, BKC = 16;   // chunk = 2 k8-steps
constexpr int SROW = 12;                       // smem row stride (floats): 0-conflict
constexpr int TILEF = 2 * BM * SROW;           // floats per (buf) per operand = 3072
constexpr int DYN_SMEM = 2 * 2 * BM * SROW * 2 * 4; // 2 ops * 2 bufs * 2 steps... = 49152
}

// ---- scratch ----------------------------------------------------------------
__device__ float g_wat[512 * 512];
__device__ float g_wbt[512 * 512];
__device__ float g_iat[NB * 512 * 2048];
__device__ float g_ibt[NB * 512 * 2048];
__device__ float g_ma[NB * NLA * NH];
__device__ float g_mb[NB * NLB * NH];
__device__ float g_s [(size_t)NB * NLA * NLB];
__device__ float g_st[(size_t)NB * NLA * NLB];
__device__ float g_rmax[NB * NLA];
__device__ float g_rinv[NB * NLA];
__device__ float g_cmax[NB * NLB];
__device__ float g_cinv[NB * NLB];

__device__ __forceinline__ float to_tf32(float x) {
    float r; asm("cvt.rna.tf32.f32 %0, %1;" : "=f"(r) : "f"(x)); return r;
}
__device__ __forceinline__ void mma_tf32(float (&d)[4],
                                         uint32_t a0, uint32_t a1, uint32_t a2, uint32_t a3,
                                         uint32_t b0, uint32_t b1) {
    asm volatile(
        "mma.sync.aligned.m16n8k8.row.col.f32.tf32.tf32.f32 "
        "{%0,%1,%2,%3}, {%4,%5,%6,%7}, {%8,%9}, {%0,%1,%2,%3};"
        : "+f"(d[0]), "+f"(d[1]), "+f"(d[2]), "+f"(d[3])
        : "r"(a0), "r"(a1), "r"(a2), "r"(a3), "r"(b0), "r"(b1));
}

// ---------------------------------------------------------------------------
// tf32 GEMM: C[m,n] = sum_k A[m,k] * B[n,k]  (+ epilogue per MODE)
// MODE 0: projections (WHICH: 0 -> g_ma, 1 -> g_mb), epi = bias
// MODE 1: scores (WHICH: 0 -> S from ma,mb ; 1 -> S^T from mb,ma), mask+scale
// MODE 2: out_a = exp(g_s - cmax[k])*cinv[k] @ g_ibt   + resid input_a
// MODE 3: out_b = exp(g_st - rmax[k])*rinv[k] @ g_iat  + resid input_b
// ---------------------------------------------------------------------------
template <int MODE, int WHICH>
__global__ void __launch_bounds__(256, 2)
tc_gemm(const float* __restrict__ X0, const float* __restrict__ X2,
        const int* __restrict__ MR, const int* __restrict__ MCm,
        float* __restrict__ OUT)
{
    constexpr int K   = (MODE <= 1) ? 512 : 2048;
    constexpr int NC  = K / BKC;
    constexpr int LDA = (MODE >= 2) ? 2048 : 512;
    constexpr int LDB = (MODE >= 2) ? 2048 : 512;
    constexpr int LDC = (MODE == 1) ? 2048 : 512;

    extern __shared__ float smem[];
    float* sA = smem;                 // [buf][step][128][SROW]
    float* sB = smem + 2 * TILEF;

    const int tid = threadIdx.x;
    const int z   = blockIdx.z;
    const int m0  = blockIdx.y * BM;
    const int n0  = blockIdx.x * BN;

    // ---- mode pointers ----
    const float* A; const float* Bm; float* C;
    const float* aux = nullptr; const float* t1 = nullptr; const float* t2 = nullptr;
    if (MODE == 0) {
        A = X0; Bm = WHICH ? g_wbt : g_wat; C = WHICH ? g_mb : g_ma; aux = X2;
    } else if (MODE == 1) {
        A  = (WHICH ? g_mb : g_ma) + (size_t)z * 2048 * 512;
        Bm = (WHICH ? g_ma : g_mb) + (size_t)z * 2048 * 512;
        C  = (WHICH ? g_st : g_s)  + (size_t)z * NLA * NLB;
    } else if (MODE == 2) {
        A  = g_s   + (size_t)z * NLA * NLB;
        Bm = g_ibt + (size_t)z * ND * NLB;
        C  = OUT   + (size_t)z * NLA * ND;
        aux = X2   + (size_t)z * NLA * ND;
        t1 = g_cmax + z * NLB;  t2 = g_cinv + z * NLB;
    } else {
        A  = g_st  + (size_t)z * NLA * NLB;
        Bm = g_iat + (size_t)z * ND * NLA;
        C  = OUT   + (size_t)z * NLB * ND;
        aux = X2   + (size_t)z * NLB * ND;
        t1 = g_rmax + z * NLA;  t2 = g_rinv + z * NLA;
    }

    // ---- producer staging ----
    const int prow = tid >> 1;            // 0..127
    const int pq   = (tid & 1) * 4;       // 0 or 4
    float4 ra[2], rb[2];

    auto loadChunk = [&](int c) {
        const int k0 = c * BKC;
        #pragma unroll
        for (int s = 0; s < 2; ++s) {
            const int col = k0 + s * 8 + pq;
            float4 v = *(const float4*)(A + (size_t)(m0 + prow) * LDA + col);
            if (MODE >= 2) {
                float4 mx = *(const float4*)(t1 + col);
                float4 iv = *(const float4*)(t2 + col);
                v.x = __expf(v.x - mx.x) * iv.x;
                v.y = __expf(v.y - mx.y) * iv.y;
                v.z = __expf(v.z - mx.z) * iv.z;
                v.w = __expf(v.w - mx.w) * iv.w;
            }
            v.x = to_tf32(v.x); v.y = to_tf32(v.y);
            v.z = to_tf32(v.z); v.w = to_tf32(v.w);
            ra[s] = v;
            float4 w = *(const float4*)(Bm + (size_t)(n0 + prow) * LDB + col);
            w.x = to_tf32(w.x); w.y = to_tf32(w.y);
            w.z = to_tf32(w.z); w.w = to_tf32(w.w);
            rb[s] = w;
        }
    };
    auto storeChunk = [&](int p) {
        #pragma unroll
        for (int s = 0; s < 2; ++s) {
            *(float4*)&sA[(p * 2 + s) * BM * SROW + prow * SROW + pq] = ra[s];
            *(float4*)&sB[(p * 2 + s) * BM * SROW + prow * SROW + pq] = rb[s];
        }
    };

    // ---- consumer identity ----
    const int warp = tid >> 5, lane = tid & 31;
    const int wm = warp >> 2, wn = warp & 3;     // 2 x 4 warp grid
    const int m_base = wm * 64, n_base = wn * 32;
    const int g = lane >> 2, tg = lane & 3;

    float acc[4][4][4] = {};

    loadChunk(0);
    storeChunk(0);
    __syncthreads();
    int p = 0;

    for (int c = 0; c < NC; ++c) {
        if (c + 1 < NC) loadChunk(c + 1);
        // ---- compute chunk from buffer p ----
        #pragma unroll
        for (int s = 0; s < 2; ++s) {
            const float* a_t = sA + (p * 2 + s) * BM * SROW;
            const float* b_t = sB + (p * 2 + s) * BM * SROW;
            uint32_t af[4][4], bf[4][2];
            #pragma unroll
            for (int mt = 0; mt < 4; ++mt) {
                const int r0 = (m_base + 16 * mt + g) * SROW;
                af[mt][0] = *(const uint32_t*)&a_t[r0 + tg];
                af[mt][1] = *(const uint32_t*)&a_t[r0 + 8 * SROW + tg];
                af[mt][2] = *(const uint32_t*)&a_t[r0 + tg + 4];
                af[mt][3] = *(const uint32_t*)&a_t[r0 + 8 * SROW + tg + 4];
            }
            #pragma unroll
            for (int nt = 0; nt < 4; ++nt) {
                const int r0 = (n_base + 8 * nt + g) * SROW;
                bf[nt][0] = *(const uint32_t*)&b_t[r0 + tg];
                bf[nt][1] = *(const uint32_t*)&b_t[r0 + tg + 4];
            }
            #pragma unroll
            for (int mt = 0; mt < 4; ++mt)
                #pragma unroll
                for (int nt = 0; nt < 4; ++nt)
                    mma_tf32(acc[mt][nt], af[mt][0], af[mt][1], af[mt][2], af[mt][3],
                             bf[nt][0], bf[nt][1]);
        }
        if (c + 1 < NC) storeChunk(p ^ 1);
        __syncthreads();
        p ^= 1;
    }

    // ---- epilogue ----
    #pragma unroll
    for (int mt = 0; mt < 4; ++mt) {
        int rmask0 = 0, rmask1 = 0;
        const int row0 = m0 + m_base + 16 * mt + g;
        if (MODE == 1) {
            rmask0 = MR[z * 2048 + row0];
            rmask1 = MR[z * 2048 + row0 + 8];
        }
        #pragma unroll
        for (int nt = 0; nt < 4; ++nt) {
            const int col0 = n0 + n_base + 8 * nt + 2 * tg;
            if (MODE == 1) {
                const int2 cm = *(const int2*)&MCm[z * 2048 + col0];
                float2 o0, o1;
                o0.x = (rmask0 * cm.x == 0) ? -1e9f : acc[mt][nt][0] * SCALE;
                o0.y = (rmask0 * cm.y == 0) ? -1e9f : acc[mt][nt][1] * SCALE;
                o1.x = (rmask1 * cm.x == 0) ? -1e9f : acc[mt][nt][2] * SCALE;
                o1.y = (rmask1 * cm.y == 0) ? -1e9f : acc[mt][nt][3] * SCALE;
                *(float2*)(C + (size_t)row0 * LDC + col0)       = o0;
                *(float2*)(C + (size_t)(row0 + 8) * LDC + col0) = o1;
            } else if (MODE == 0) {
                const float2 bv = *(const float2*)(aux + col0);
                float2 o0 = make_float2(acc[mt][nt][0] + bv.x, acc[mt][nt][1] + bv.y);
                float2 o1 = make_float2(acc[mt][nt][2] + bv.x, acc[mt][nt][3] + bv.y);
                *(float2*)(C + (size_t)row0 * LDC + col0)       = o0;
                *(float2*)(C + (size_t)(row0 + 8) * LDC + col0) = o1;
            } else {
                const float2 e0 = *(const float2*)(aux + (size_t)row0 * 512 + col0);
                const float2 e1 = *(const float2*)(aux + (size_t)(row0 + 8) * 512 + col0);
                float2 o0 = make_float2(acc[mt][nt][0] + e0.x, acc[mt][nt][1] + e0.y);
                float2 o1 = make_float2(acc[mt][nt][2] + e1.x, acc[mt][nt][3] + e1.y);
                *(float2*)(C + (size_t)row0 * LDC + col0)       = o0;
                *(float2*)(C + (size_t)(row0 + 8) * LDC + col0) = o1;
            }
        }
    }
}

// ---------------------------------------------------------------------------
template <int DSTSEL>
__global__ void __launch_bounds__(256) transpose_k(const float* __restrict__ src,
                                                   int R, int C)
{
    __shared__ float tile[32][33];
    float* dstbase = (DSTSEL == 0) ? g_wat : (DSTSEL == 1) ? g_wbt
                   : (DSTSEL == 2) ? g_iat : g_ibt;
    const int z = blockIdx.z;
    const float* s = src + (size_t)z * R * C;
    float* d = dstbase + (size_t)z * R * C;

    int x = blockIdx.x * 32 + threadIdx.x;
    int y = blockIdx.y * 32 + threadIdx.y;
    #pragma unroll
    for (int j = 0; j < 32; j += 8)
        tile[threadIdx.y + j][threadIdx.x] = s[(size_t)(y + j) * C + x];
    __syncthreads();
    x = blockIdx.y * 32 + threadIdx.x;
    y = blockIdx.x * 32 + threadIdx.y;
    #pragma unroll
    for (int j = 0; j < 32; j += 8)
        d[(size_t)(y + j) * R + x] = tile[threadIdx.x][threadIdx.y + j];
}

// ---------------------------------------------------------------------------
template <int SEL>
__global__ void __launch_bounds__(256) rowstats_k()
{
    const float* S = SEL ? g_st : g_s;
    float* omax = SEL ? g_cmax : g_rmax;
    float* oinv = SEL ? g_cinv : g_rinv;

    const int warp = threadIdx.x >> 5;
    const int lane = threadIdx.x & 31;
    const int row  = blockIdx.x * 8 + warp;
    const float* pr = S + (size_t)row * 2048;

    float m = -1e30f, l = 0.f;
    for (int c = lane * 4; c < 2048; c += 128) {
        float4 v = *(const float4*)(pr + c);
        float mv = fmaxf(fmaxf(v.x, v.y), fmaxf(v.z, v.w));
        float nm = fmaxf(m, mv);
        l = l * __expf(m - nm)
          + __expf(v.x - nm) + __expf(v.y - nm)
          + __expf(v.z - nm) + __expf(v.w - nm);
        m = nm;
    }
    #pragma unroll
    for (int o = 16; o; o >>= 1) {
        float om = __shfl_xor_sync(0xffffffffu, m, o);
        float ol = __shfl_xor_sync(0xffffffffu, l, o);
        float nm = fmaxf(m, om);
        l = l * __expf(m - nm) + ol * __expf(om - nm);
        m = nm;
    }
    if (lane == 0) { omax[row] = m; oinv[row] = 1.f / l; }
}

// ---------------------------------------------------------------------------
extern "C" void kernel_launch(void* const* d_in, const int* in_sizes, int n_in,
                              void* d_out, int out_size)
{
    (void)in_sizes; (void)n_in; (void)out_size;
    const float* input_a = (const float*)d_in[0];
    const float* input_b = (const float*)d_in[1];
    const int*   mask_a  = (const int*)d_in[2];
    const int*   mask_b  = (const int*)d_in[3];
    const float* Wa      = (const float*)d_in[4];
    const float* ba      = (const float*)d_in[5];
    const float* Wb      = (const float*)d_in[6];
    const float* bb      = (const float*)d_in[7];
    float* out = (float*)d_out;

    static bool attr_done = false;
    if (!attr_done) {
        cudaFuncSetAttribute(tc_gemm<0,0>, cudaFuncAttributeMaxDynamicSharedMemorySize, DYN_SMEM);
        cudaFuncSetAttribute(tc_gemm<0,1>, cudaFuncAttributeMaxDynamicSharedMemorySize, DYN_SMEM);
        cudaFuncSetAttribute(tc_gemm<1,0>, cudaFuncAttributeMaxDynamicSharedMemorySize, DYN_SMEM);
        cudaFuncSetAttribute(tc_gemm<1,1>, cudaFuncAttributeMaxDynamicSharedMemorySize, DYN_SMEM);
        cudaFuncSetAttribute(tc_gemm<2,0>, cudaFuncAttributeMaxDynamicSharedMemorySize, DYN_SMEM);
        cudaFuncSetAttribute(tc_gemm<3,0>, cudaFuncAttributeMaxDynamicSharedMemorySize, DYN_SMEM);
        attr_done = true;
    }

    // transposes: W^T and input^T
    transpose_k<0><<<dim3(16, 16, 1),  dim3(32, 8)>>>(Wa, 512, 512);
    transpose_k<1><<<dim3(16, 16, 1),  dim3(32, 8)>>>(Wb, 512, 512);
    transpose_k<2><<<dim3(16, 64, NB), dim3(32, 8)>>>(input_a, 2048, 512);
    transpose_k<3><<<dim3(16, 64, NB), dim3(32, 8)>>>(input_b, 2048, 512);

    // projections
    tc_gemm<0,0><<<dim3(4, 128, 1), 256, DYN_SMEM>>>(input_a, ba, nullptr, nullptr, nullptr);
    tc_gemm<0,1><<<dim3(4, 128, 1), 256, DYN_SMEM>>>(input_b, bb, nullptr, nullptr, nullptr);

    // masked scaled scores, both orientations
    tc_gemm<1,0><<<dim3(16, 16, NB), 256, DYN_SMEM>>>(nullptr, nullptr, mask_a, mask_b, nullptr);
    tc_gemm<1,1><<<dim3(16, 16, NB), 256, DYN_SMEM>>>(nullptr, nullptr, mask_b, mask_a, nullptr);

    // softmax stats
    rowstats_k<0><<<(NB * NLA) / 8, 256>>>();
    rowstats_k<1><<<(NB * NLB) / 8, 256>>>();

    // attention-weighted outputs + residual
    tc_gemm<2,0><<<dim3(4, 16, NB), 256, DYN_SMEM>>>(nullptr, input_a, nullptr, nullptr, out);
    tc_gemm<3,0><<<dim3(4, 16, NB), 256, DYN_SMEM>>>(nullptr, input_b, nullptr, nullptr,
                                                     out + (size_t)NB * NLA * ND);
}

// round 4
// speedup vs baseline: 3.3184x; 1.6934x over previous
#include <cuda_runtime.h>
#include <cuda_fp16.h>
#include <cstdint>

// ---------------------------------------------------------------------------
// CrossAttention via mma.sync fp16 (m16n8k16, fp32 accum).
// Max-free softmax: scores kernel stores E = exp(scale*s) (masked -> exp(-30)),
// plus E^T via smem transpose; stats are plain row sums.
// ---------------------------------------------------------------------------

namespace {
constexpr int NB = 8, NLA = 2048, NLB = 2048, ND = 512, NH = 512;
constexpr float SCALE = 0.04419417382415922f;   // 1/sqrt(512)
constexpr float EXPM  = 9.357622969e-14f;        // exp(-30), masked-entry value

constexpr int BM = 128, BN = 128, BK = 32;       // chunk = 2 k16 steps
constexpr int W2 = 40;                            // smem row stride in halfs (20 words)
constexpr int OPH = BM * W2;                      // halfs per operand per buffer = 5120
constexpr int PIPE_SMEM = 2 * 2 * OPH * 2;        // bytes: 2 bufs * 2 ops = 40960
constexpr int TILE_SMEM = 128 * 129 * 4;          // scores transpose tile = 66048
}

// ---- scratch ----------------------------------------------------------------
__device__ float g_wat[512 * 512];
__device__ float g_wbt[512 * 512];
__device__ float g_iat[NB * 512 * 2048];
__device__ float g_ibt[NB * 512 * 2048];
__device__ float g_ma[NB * NLA * NH];
__device__ float g_mb[NB * NLB * NH];
__device__ float g_s [(size_t)NB * NLA * NLB];   // E[i][j]
__device__ float g_st[(size_t)NB * NLA * NLB];   // E^T[j][i]
__device__ float g_rinv[NB * NLA];               // 1/sum_j E[i][j]
__device__ float g_cinv[NB * NLB];               // 1/sum_i E[i][j]

__device__ __forceinline__ void mma_f16(float (&d)[4],
                                        uint32_t a0, uint32_t a1, uint32_t a2, uint32_t a3,
                                        uint32_t b0, uint32_t b1) {
    asm volatile(
        "mma.sync.aligned.m16n8k16.row.col.f32.f16.f16.f32 "
        "{%0,%1,%2,%3}, {%4,%5,%6,%7}, {%8,%9}, {%0,%1,%2,%3};"
        : "+f"(d[0]), "+f"(d[1]), "+f"(d[2]), "+f"(d[3])
        : "r"(a0), "r"(a1), "r"(a2), "r"(a3), "r"(b0), "r"(b1));
}
__device__ __forceinline__ uint32_t pack_h2(float x, float y) {
    __half2 h = __floats2half2_rn(x, y);
    return *reinterpret_cast<uint32_t*>(&h);
}

// ---------------------------------------------------------------------------
// fp16 GEMM: C[m,n] = sum_k A[m,k] * B[n,k]  (+ epilogue per MODE)
// MODE 0: projections (WHICH 0: g_ma, 1: g_mb), epi = bias
// MODE 1: scores: E = exp(scale*ma.mb^T) masked->EXPM; writes g_s AND g_st
// MODE 2: out_a = (E * cinv[k]) @ g_ibt + resid input_a
// MODE 3: out_b = (E^T * rinv[k]) @ g_iat + resid input_b
// ---------------------------------------------------------------------------
template <int MODE, int WHICH>
__global__ void __launch_bounds__(256, 2)
tc_gemm(const float* __restrict__ X0, const float* __restrict__ X2,
        const int* __restrict__ MR, const int* __restrict__ MCm,
        float* __restrict__ OUT)
{
    constexpr int K   = (MODE <= 1) ? 512 : 2048;
    constexpr int NC  = K / BK;
    constexpr int LDA = (MODE >= 2) ? 2048 : 512;
    constexpr int LDB = (MODE >= 2) ? 2048 : 512;
    constexpr int LDC = (MODE == 1) ? 2048 : 512;

    extern __shared__ __align__(16) char smem_raw[];
    __half* sA = (__half*)smem_raw;            // [buf][128][W2]
    __half* sB = sA + 2 * OPH;

    const int tid = threadIdx.x;
    const int z   = blockIdx.z;
    const int m0  = blockIdx.y * BM;
    const int n0  = blockIdx.x * BN;

    // ---- mode pointers ----
    const float* A; const float* Bm; float* C;
    const float* aux = nullptr; const float* t2 = nullptr;
    if (MODE == 0) {
        A = X0; Bm = WHICH ? g_wbt : g_wat; C = WHICH ? g_mb : g_ma; aux = X2;
    } else if (MODE == 1) {
        A  = g_ma + (size_t)z * 2048 * 512;
        Bm = g_mb + (size_t)z * 2048 * 512;
        C  = g_s  + (size_t)z * NLA * NLB;
    } else if (MODE == 2) {
        A  = g_s   + (size_t)z * NLA * NLB;
        Bm = g_ibt + (size_t)z * ND * NLB;
        C  = OUT   + (size_t)z * NLA * ND;
        aux = X2   + (size_t)z * NLA * ND;
        t2 = g_cinv + z * NLB;
    } else {
        A  = g_st  + (size_t)z * NLA * NLB;
        Bm = g_iat + (size_t)z * ND * NLA;
        C  = OUT   + (size_t)z * NLB * ND;
        aux = X2   + (size_t)z * NLB * ND;
        t2 = g_rinv + z * NLA;
    }

    // ---- producer staging: thread owns half a row (16 halfs) per operand ----
    const int prow = tid >> 1;             // 0..127
    const int pkh  = (tid & 1) * 16;       // k-half offset 0 / 16
    uint4 ra[2], rb[2];                    // 16 halfs each operand

    auto loadChunk = [&](int c) {
        const int k0 = c * BK;
        #pragma unroll
        for (int q = 0; q < 2; ++q) {      // two 8-half groups
            uint32_t w[4];
            #pragma unroll
            for (int j = 0; j < 2; ++j) {
                const int col = k0 + pkh + q * 8 + j * 4;
                float4 v = *(const float4*)(A + (size_t)(m0 + prow) * LDA + col);
                if (MODE >= 2) {
                    float4 iv = *(const float4*)(t2 + col);
                    v.x *= iv.x; v.y *= iv.y; v.z *= iv.z; v.w *= iv.w;
                }
                w[2 * j + 0] = pack_h2(v.x, v.y);
                w[2 * j + 1] = pack_h2(v.z, v.w);
            }
            ra[q] = make_uint4(w[0], w[1], w[2], w[3]);
            #pragma unroll
            for (int j = 0; j < 2; ++j) {
                const int col = k0 + pkh + q * 8 + j * 4;
                float4 v = *(const float4*)(Bm + (size_t)(n0 + prow) * LDB + col);
                w[2 * j + 0] = pack_h2(v.x, v.y);
                w[2 * j + 1] = pack_h2(v.z, v.w);
            }
            rb[q] = make_uint4(w[0], w[1], w[2], w[3]);
        }
    };
    auto storeChunk = [&](int p) {
        uint32_t* da = (uint32_t*)(sA + p * OPH) + prow * 20 + (pkh >> 1);
        uint32_t* db = (uint32_t*)(sB + p * OPH) + prow * 20 + (pkh >> 1);
        *(uint4*)(da)     = ra[0];
        *(uint4*)(da + 4) = ra[1];
        *(uint4*)(db)     = rb[0];
        *(uint4*)(db + 4) = rb[1];
    };

    // ---- consumer identity ----
    const int warp = tid >> 5, lane = tid & 31;
    const int wm = warp >> 2, wn = warp & 3;       // 2 x 4 warp grid
    const int m_base = wm * 64, n_base = wn * 32;
    const int g = lane >> 2, tg = lane & 3;

    float acc[4][4][4] = {};

    loadChunk(0);
    storeChunk(0);
    __syncthreads();
    int p = 0;

    for (int c = 0; c < NC; ++c) {
        if (c + 1 < NC) loadChunk(c + 1);
        #pragma unroll
        for (int s = 0; s < 2; ++s) {              // two k16 steps
            const uint32_t* a_t = (const uint32_t*)(sA + p * OPH) + s * 8;
            const uint32_t* b_t = (const uint32_t*)(sB + p * OPH) + s * 8;
            uint32_t af[4][4], bf[4][2];
            #pragma unroll
            for (int mt = 0; mt < 4; ++mt) {
                const int r0 = (m_base + 16 * mt + g) * 20;
                af[mt][0] = a_t[r0 + tg];
                af[mt][1] = a_t[r0 + 8 * 20 + tg];
                af[mt][2] = a_t[r0 + tg + 4];
                af[mt][3] = a_t[r0 + 8 * 20 + tg + 4];
            }
            #pragma unroll
            for (int nt = 0; nt < 4; ++nt) {
                const int r0 = (n_base + 8 * nt + g) * 20;
                bf[nt][0] = b_t[r0 + tg];
                bf[nt][1] = b_t[r0 + tg + 4];
            }
            #pragma unroll
            for (int mt = 0; mt < 4; ++mt)
                #pragma unroll
                for (int nt = 0; nt < 4; ++nt)
                    mma_f16(acc[mt][nt], af[mt][0], af[mt][1], af[mt][2], af[mt][3],
                            bf[nt][0], bf[nt][1]);
        }
        if (c + 1 < NC) storeChunk(p ^ 1);
        __syncthreads();
        p ^= 1;
    }

    // ---- epilogue ----
    if (MODE == 1) {
        float* tile = (float*)smem_raw;            // [128][129], aliases pipeline
        #pragma unroll
        for (int mt = 0; mt < 4; ++mt) {
            const int row0 = m0 + m_base + 16 * mt + g;
            const int rm0 = MR[z * 2048 + row0];
            const int rm1 = MR[z * 2048 + row0 + 8];
            #pragma unroll
            for (int nt = 0; nt < 4; ++nt) {
                const int col0 = n0 + n_base + 8 * nt + 2 * tg;
                const int2 cm = *(const int2*)&MCm[z * 2048 + col0];
                float e00 = (rm0 * cm.x == 0) ? EXPM : __expf(acc[mt][nt][0] * SCALE);
                float e01 = (rm0 * cm.y == 0) ? EXPM : __expf(acc[mt][nt][1] * SCALE);
                float e10 = (rm1 * cm.x == 0) ? EXPM : __expf(acc[mt][nt][2] * SCALE);
                float e11 = (rm1 * cm.y == 0) ? EXPM : __expf(acc[mt][nt][3] * SCALE);
                *(float2*)(C + (size_t)row0 * LDC + col0)       = make_float2(e00, e01);
                *(float2*)(C + (size_t)(row0 + 8) * LDC + col0) = make_float2(e10, e11);
                const int li = m_base + 16 * mt + g;
                const int lj = n_base + 8 * nt + 2 * tg;
                tile[li * 129 + lj]           = e00;
                tile[li * 129 + lj + 1]       = e01;
                tile[(li + 8) * 129 + lj]     = e10;
                tile[(li + 8) * 129 + lj + 1] = e11;
            }
        }
        __syncthreads();
        // E^T: warp handles 4 j-rows, coalesced float4 stores along i
        float* CT = g_st + (size_t)z * NLA * NLB;
        const int jrow = warp * 4 + (lane >> 3);       // 0..31, x4 loop
        const int iofs = (lane & 7) * 4;
        for (int jj = jrow; jj < 128; jj += 32) {
            #pragma unroll
            for (int i0 = iofs; i0 < 128; i0 += 32) {
                float4 v;
                v.x = tile[(i0 + 0) * 129 + jj];
                v.y = tile[(i0 + 1) * 129 + jj];
                v.z = tile[(i0 + 2) * 129 + jj];
                v.w = tile[(i0 + 3) * 129 + jj];
                *(float4*)(CT + (size_t)(n0 + jj) * 2048 + m0 + i0) = v;
            }
        }
    } else {
        #pragma unroll
        for (int mt = 0; mt < 4; ++mt) {
            const int row0 = m0 + m_base + 16 * mt + g;
            #pragma unroll
            for (int nt = 0; nt < 4; ++nt) {
                const int col0 = n0 + n_base + 8 * nt + 2 * tg;
                if (MODE == 0) {
                    const float2 bv = *(const float2*)(aux + col0);
                    *(float2*)(C + (size_t)row0 * LDC + col0) =
                        make_float2(acc[mt][nt][0] + bv.x, acc[mt][nt][1] + bv.y);
                    *(float2*)(C + (size_t)(row0 + 8) * LDC + col0) =
                        make_float2(acc[mt][nt][2] + bv.x, acc[mt][nt][3] + bv.y);
                } else {
                    const float2 e0 = *(const float2*)(aux + (size_t)row0 * 512 + col0);
                    const float2 e1 = *(const float2*)(aux + (size_t)(row0 + 8) * 512 + col0);
                    *(float2*)(C + (size_t)row0 * LDC + col0) =
                        make_float2(acc[mt][nt][0] + e0.x, acc[mt][nt][1] + e0.y);
                    *(float2*)(C + (size_t)(row0 + 8) * LDC + col0) =
                        make_float2(acc[mt][nt][2] + e1.x, acc[mt][nt][3] + e1.y);
                }
            }
        }
    }
}

// ---------------------------------------------------------------------------
template <int DSTSEL>
__global__ void __launch_bounds__(256) transpose_k(const float* __restrict__ src,
                                                   int R, int C)
{
    __shared__ float tile[32][33];
    float* dstbase = (DSTSEL == 0) ? g_wat : (DSTSEL == 1) ? g_wbt
                   : (DSTSEL == 2) ? g_iat : g_ibt;
    const int z = blockIdx.z;
    const float* s = src + (size_t)z * R * C;
    float* d = dstbase + (size_t)z * R * C;

    int x = blockIdx.x * 32 + threadIdx.x;
    int y = blockIdx.y * 32 + threadIdx.y;
    #pragma unroll
    for (int j = 0; j < 32; j += 8)
        tile[threadIdx.y + j][threadIdx.x] = s[(size_t)(y + j) * C + x];
    __syncthreads();
    x = blockIdx.y * 32 + threadIdx.x;
    y = blockIdx.x * 32 + threadIdx.y;
    #pragma unroll
    for (int j = 0; j < 32; j += 8)
        d[(size_t)(y + j) * R + x] = tile[threadIdx.x][threadIdx.y + j];
}

// ---------------------------------------------------------------------------
// Plain row sums of E (2048-wide); out = 1/sum.  SEL 0: g_s->g_rinv, 1: g_st->g_cinv
// ---------------------------------------------------------------------------
template <int SEL>
__global__ void __launch_bounds__(256) rowsum_k()
{
    const float* S = SEL ? g_st : g_s;
    float* oinv = SEL ? g_cinv : g_rinv;

    const int warp = threadIdx.x >> 5;
    const int lane = threadIdx.x & 31;
    const int row  = blockIdx.x * 8 + warp;
    const float* pr = S + (size_t)row * 2048;

    float l = 0.f;
    for (int c = lane * 4; c < 2048; c += 128) {
        float4 v = *(const float4*)(pr + c);
        l += (v.x + v.y) + (v.z + v.w);
    }
    #pragma unroll
    for (int o = 16; o; o >>= 1)
        l += __shfl_xor_sync(0xffffffffu, l, o);
    if (lane == 0) oinv[row] = 1.f / l;
}

// ---------------------------------------------------------------------------
extern "C" void kernel_launch(void* const* d_in, const int* in_sizes, int n_in,
                              void* d_out, int out_size)
{
    (void)in_sizes; (void)n_in; (void)out_size;
    const float* input_a = (const float*)d_in[0];
    const float* input_b = (const float*)d_in[1];
    const int*   mask_a  = (const int*)d_in[2];
    const int*   mask_b  = (const int*)d_in[3];
    const float* Wa      = (const float*)d_in[4];
    const float* ba      = (const float*)d_in[5];
    const float* Wb      = (const float*)d_in[6];
    const float* bb      = (const float*)d_in[7];
    float* out = (float*)d_out;

    static bool attr_done = false;
    if (!attr_done) {
        cudaFuncSetAttribute(tc_gemm<0,0>, cudaFuncAttributeMaxDynamicSharedMemorySize, PIPE_SMEM);
        cudaFuncSetAttribute(tc_gemm<0,1>, cudaFuncAttributeMaxDynamicSharedMemorySize, PIPE_SMEM);
        cudaFuncSetAttribute(tc_gemm<1,0>, cudaFuncAttributeMaxDynamicSharedMemorySize, TILE_SMEM);
        cudaFuncSetAttribute(tc_gemm<2,0>, cudaFuncAttributeMaxDynamicSharedMemorySize, PIPE_SMEM);
        cudaFuncSetAttribute(tc_gemm<3,0>, cudaFuncAttributeMaxDynamicSharedMemorySize, PIPE_SMEM);
        attr_done = true;
    }

    // transposes: W^T and input^T
    transpose_k<0><<<dim3(16, 16, 1),  dim3(32, 8)>>>(Wa, 512, 512);
    transpose_k<1><<<dim3(16, 16, 1),  dim3(32, 8)>>>(Wb, 512, 512);
    transpose_k<2><<<dim3(16, 64, NB), dim3(32, 8)>>>(input_a, 2048, 512);
    transpose_k<3><<<dim3(16, 64, NB), dim3(32, 8)>>>(input_b, 2048, 512);

    // projections
    tc_gemm<0,0><<<dim3(4, 128, 1), 256, PIPE_SMEM>>>(input_a, ba, nullptr, nullptr, nullptr);
    tc_gemm<0,1><<<dim3(4, 128, 1), 256, PIPE_SMEM>>>(input_b, bb, nullptr, nullptr, nullptr);

    // masked exp-scores -> g_s and g_st (single GEMM, fused transpose)
    tc_gemm<1,0><<<dim3(16, 16, NB), 256, TILE_SMEM>>>(nullptr, nullptr, mask_a, mask_b, nullptr);

    // softmax denominators (plain sums)
    rowsum_k<0><<<(NB * NLA) / 8, 256>>>();
    rowsum_k<1><<<(NB * NLB) / 8, 256>>>();

    // attention-weighted outputs + residual
    tc_gemm<2,0><<<dim3(4, 16, NB), 256, PIPE_SMEM>>>(nullptr, input_a, nullptr, nullptr, out);
    tc_gemm<3,0><<<dim3(4, 16, NB), 256, PIPE_SMEM>>>(nullptr, input_b, nullptr, nullptr,
                                                      out + (size_t)NB * NLA * ND);
}

// round 5
// speedup vs baseline: 4.6178x; 1.3916x over previous
#include <cuda_runtime.h>
#include <cuda_fp16.h>
#include <cstdint>

// ---------------------------------------------------------------------------
// CrossAttention, fp16-everywhere dataflow:
//   proj (fp32 in, fp16 out) -> E=exp(scale*s) fp16 + E^T fp16 + fused sums
//   -> recip -> AV GEMMs (fp16 operands, fp32 out + residual).
// ---------------------------------------------------------------------------

namespace {
constexpr int NB = 8, NLA = 2048, NLB = 2048, ND = 512, NH = 512;
constexpr float SCALE = 0.04419417382415922f;   // 1/sqrt(512)
constexpr float EXPM  = 1e-6f;                   // masked-entry E value (fp16-safe)

constexpr int BM = 128, BN = 128, BK = 32;       // chunk = 2 k16 steps
constexpr int W2 = 40;                            // smem row stride (halfs)
constexpr int OPH = BM * W2;                      // halfs per operand per buffer
constexpr int PIPE_SMEM = 2 * 2 * OPH * 2;        // 40960 B
constexpr int TILE_SMEM = 128 * 129 * 4;          // 66048 B (scores transpose)
}

// ---- scratch ----------------------------------------------------------------
__device__ __half g_wat[512 * 512];
__device__ __half g_wbt[512 * 512];
__device__ __half g_iat[NB * 512 * 2048];
__device__ __half g_ibt[NB * 512 * 2048];
__device__ __half g_ma[NB * NLA * NH];
__device__ __half g_mb[NB * NLB * NH];
__device__ __half g_s [(size_t)NB * NLA * NLB];   // E[i][j]
__device__ __half g_st[(size_t)NB * NLA * NLB];   // E^T[j][i]
__device__ float g_rsum[NB * NLA];
__device__ float g_csum[NB * NLB];
__device__ float g_rinv[NB * NLA];
__device__ float g_cinv[NB * NLB];

__device__ __forceinline__ void mma_f16(float (&d)[4],
                                        uint32_t a0, uint32_t a1, uint32_t a2, uint32_t a3,
                                        uint32_t b0, uint32_t b1) {
    asm volatile(
        "mma.sync.aligned.m16n8k16.row.col.f32.f16.f16.f32 "
        "{%0,%1,%2,%3}, {%4,%5,%6,%7}, {%8,%9}, {%0,%1,%2,%3};"
        : "+f"(d[0]), "+f"(d[1]), "+f"(d[2]), "+f"(d[3])
        : "r"(a0), "r"(a1), "r"(a2), "r"(a3), "r"(b0), "r"(b1));
}
__device__ __forceinline__ uint32_t pack_h2(float x, float y) {
    __half2 h = __floats2half2_rn(x, y);
    return *reinterpret_cast<uint32_t*>(&h);
}

// ---------------------------------------------------------------------------
// fp16 GEMM: C[m,n] = sum_k A[m,k] * B[n,k]
// MODE 0: proj (WHICH 0: g_ma, 1: g_mb), A fp32 input, B=g_w?t, epi bias -> fp16
// MODE 1: scores: E = exp(scale*ma.mb^T) masked->EXPM; writes g_s, g_st, sums
// MODE 2: out_a = (E * cinv[k]) @ g_ibt + resid input_a   (fp32 out)
// MODE 3: out_b = (E^T * rinv[k]) @ g_iat + resid input_b (fp32 out)
// ---------------------------------------------------------------------------
template <int MODE, int WHICH>
__global__ void __launch_bounds__(256, 2)
tc_gemm(const float* __restrict__ X0, const float* __restrict__ X2,
        const int* __restrict__ MR, const int* __restrict__ MCm,
        float* __restrict__ OUT)
{
    constexpr int K   = (MODE <= 1) ? 512 : 2048;
    constexpr int NC  = K / BK;
    constexpr int LDA = (MODE >= 2) ? 2048 : 512;
    constexpr int LDB = (MODE >= 2) ? 2048 : 512;

    extern __shared__ __align__(16) char smem_raw[];
    __half* sA = (__half*)smem_raw;            // [buf][128][W2]
    __half* sB = sA + 2 * OPH;

    const int tid = threadIdx.x;
    const int z   = blockIdx.z;
    const int m0  = blockIdx.y * BM;
    const int n0  = blockIdx.x * BN;

    // ---- mode pointers ----
    const float*  Af = nullptr;     // fp32 A (MODE 0)
    const __half* Ah = nullptr;     // fp16 A (MODE 1..3)
    const __half* Bh;               // fp16 B (all modes)
    const float* aux = nullptr; const float* t2 = nullptr;
    __half* Ch = nullptr; float* Cf = nullptr;
    if (MODE == 0) {
        Af = X0; Bh = WHICH ? g_wbt : g_wat; Ch = WHICH ? g_mb : g_ma; aux = X2;
    } else if (MODE == 1) {
        Ah = g_ma + (size_t)z * 2048 * 512;
        Bh = g_mb + (size_t)z * 2048 * 512;
        Ch = g_s  + (size_t)z * NLA * NLB;
    } else if (MODE == 2) {
        Ah = g_s   + (size_t)z * NLA * NLB;
        Bh = g_ibt + (size_t)z * ND * NLB;
        Cf = OUT   + (size_t)z * NLA * ND;
        aux = X2   + (size_t)z * NLA * ND;
        t2 = g_cinv + z * NLB;
    } else {
        Ah = g_st  + (size_t)z * NLA * NLB;
        Bh = g_iat + (size_t)z * ND * NLA;
        Cf = OUT   + (size_t)z * NLB * ND;
        aux = X2   + (size_t)z * NLB * ND;
        t2 = g_rinv + z * NLA;
    }

    // ---- producer staging: thread owns 16 halfs per operand per chunk ----
    const int prow = tid >> 1;             // 0..127
    const int pkh  = (tid & 1) * 16;       // k-half offset 0 / 16
    uint4 ra[2], rb[2];

    auto loadChunk = [&](int c) {
        const int k0 = c * BK;
        if (MODE == 0) {
            #pragma unroll
            for (int q = 0; q < 2; ++q) {
                uint32_t w[4];
                #pragma unroll
                for (int j = 0; j < 2; ++j) {
                    const int col = k0 + pkh + q * 8 + j * 4;
                    float4 v = *(const float4*)(Af + (size_t)(m0 + prow) * LDA + col);
                    w[2 * j + 0] = pack_h2(v.x, v.y);
                    w[2 * j + 1] = pack_h2(v.z, v.w);
                }
                ra[q] = make_uint4(w[0], w[1], w[2], w[3]);
            }
        } else {
            const uint4* ap = (const uint4*)(Ah + (size_t)(m0 + prow) * LDA + k0 + pkh);
            ra[0] = ap[0]; ra[1] = ap[1];
            if (MODE >= 2) {
                float iv[16];
                const float4* tp4 = (const float4*)(t2 + k0 + pkh);
                *(float4*)&iv[0]  = tp4[0];
                *(float4*)&iv[4]  = tp4[1];
                *(float4*)&iv[8]  = tp4[2];
                *(float4*)&iv[12] = tp4[3];
                #pragma unroll
                for (int q = 0; q < 2; ++q) {
                    __half2* hp = (__half2*)&ra[q];
                    #pragma unroll
                    for (int j = 0; j < 4; ++j) {
                        float2 f = __half22float2(hp[j]);
                        f.x *= iv[q * 8 + 2 * j];
                        f.y *= iv[q * 8 + 2 * j + 1];
                        hp[j] = __floats2half2_rn(f.x, f.y);
                    }
                }
            }
        }
        const uint4* bp = (const uint4*)(Bh + (size_t)(n0 + prow) * LDB + k0 + pkh);
        rb[0] = bp[0]; rb[1] = bp[1];
    };
    auto storeChunk = [&](int p) {
        uint32_t* da = (uint32_t*)(sA + p * OPH) + prow * 20 + (pkh >> 1);
        uint32_t* db = (uint32_t*)(sB + p * OPH) + prow * 20 + (pkh >> 1);
        *(uint4*)(da)     = ra[0];
        *(uint4*)(da + 4) = ra[1];
        *(uint4*)(db)     = rb[0];
        *(uint4*)(db + 4) = rb[1];
    };

    // ---- consumer identity ----
    const int warp = tid >> 5, lane = tid & 31;
    const int wm = warp >> 2, wn = warp & 3;       // 2 x 4 warp grid
    const int m_base = wm * 64, n_base = wn * 32;
    const int g = lane >> 2, tg = lane & 3;

    float acc[4][4][4] = {};

    loadChunk(0);
    storeChunk(0);
    __syncthreads();
    int p = 0;

    for (int c = 0; c < NC; ++c) {
        if (c + 1 < NC) loadChunk(c + 1);
        #pragma unroll
        for (int s = 0; s < 2; ++s) {
            const uint32_t* a_t = (const uint32_t*)(sA + p * OPH) + s * 8;
            const uint32_t* b_t = (const uint32_t*)(sB + p * OPH) + s * 8;
            uint32_t af[4][4], bf[4][2];
            #pragma unroll
            for (int mt = 0; mt < 4; ++mt) {
                const int r0 = (m_base + 16 * mt + g) * 20;
                af[mt][0] = a_t[r0 + tg];
                af[mt][1] = a_t[r0 + 8 * 20 + tg];
                af[mt][2] = a_t[r0 + tg + 4];
                af[mt][3] = a_t[r0 + 8 * 20 + tg + 4];
            }
            #pragma unroll
            for (int nt = 0; nt < 4; ++nt) {
                const int r0 = (n_base + 8 * nt + g) * 20;
                bf[nt][0] = b_t[r0 + tg];
                bf[nt][1] = b_t[r0 + tg + 4];
            }
            #pragma unroll
            for (int mt = 0; mt < 4; ++mt)
                #pragma unroll
                for (int nt = 0; nt < 4; ++nt)
                    mma_f16(acc[mt][nt], af[mt][0], af[mt][1], af[mt][2], af[mt][3],
                            bf[nt][0], bf[nt][1]);
        }
        if (c + 1 < NC) storeChunk(p ^ 1);
        __syncthreads();
        p ^= 1;
    }

    // ---- epilogue ----
    if (MODE == 1) {
        float* tile = (float*)smem_raw;            // [128][129]
        float csum0[4] = {0.f, 0.f, 0.f, 0.f};
        float csum1[4] = {0.f, 0.f, 0.f, 0.f};
        #pragma unroll
        for (int mt = 0; mt < 4; ++mt) {
            const int row0 = m0 + m_base + 16 * mt + g;
            const int rm0 = MR[z * 2048 + row0];
            const int rm1 = MR[z * 2048 + row0 + 8];
            float rsum0 = 0.f, rsum1 = 0.f;
            #pragma unroll
            for (int nt = 0; nt < 4; ++nt) {
                const int col0 = n0 + n_base + 8 * nt + 2 * tg;
                const int2 cm = *(const int2*)&MCm[z * 2048 + col0];
                float e00 = (rm0 * cm.x == 0) ? EXPM : __expf(acc[mt][nt][0] * SCALE);
                float e01 = (rm0 * cm.y == 0) ? EXPM : __expf(acc[mt][nt][1] * SCALE);
                float e10 = (rm1 * cm.x == 0) ? EXPM : __expf(acc[mt][nt][2] * SCALE);
                float e11 = (rm1 * cm.y == 0) ? EXPM : __expf(acc[mt][nt][3] * SCALE);
                __half2 p0 = __floats2half2_rn(e00, e01);
                __half2 p1 = __floats2half2_rn(e10, e11);
                *(__half2*)(Ch + (size_t)row0 * 2048 + col0)       = p0;
                *(__half2*)(Ch + (size_t)(row0 + 8) * 2048 + col0) = p1;
                // rounded values (what AV will read) feed sums + transpose
                float2 r0 = __half22float2(p0);
                float2 r1 = __half22float2(p1);
                const int li = m_base + 16 * mt + g;
                const int lj = n_base + 8 * nt + 2 * tg;
                tile[li * 129 + lj]           = r0.x;
                tile[li * 129 + lj + 1]       = r0.y;
                tile[(li + 8) * 129 + lj]     = r1.x;
                tile[(li + 8) * 129 + lj + 1] = r1.y;
                rsum0 += r0.x + r0.y;
                rsum1 += r1.x + r1.y;
                csum0[nt] += r0.x + r1.x;
                csum1[nt] += r0.y + r1.y;
            }
            rsum0 += __shfl_xor_sync(0xffffffffu, rsum0, 1);
            rsum0 += __shfl_xor_sync(0xffffffffu, rsum0, 2);
            rsum1 += __shfl_xor_sync(0xffffffffu, rsum1, 1);
            rsum1 += __shfl_xor_sync(0xffffffffu, rsum1, 2);
            if (tg == 0) {
                atomicAdd(&g_rsum[z * 2048 + row0],     rsum0);
                atomicAdd(&g_rsum[z * 2048 + row0 + 8], rsum1);
            }
        }
        #pragma unroll
        for (int nt = 0; nt < 4; ++nt) {
            float c0 = csum0[nt], c1 = csum1[nt];
            #pragma unroll
            for (int o = 4; o <= 16; o <<= 1) {
                c0 += __shfl_xor_sync(0xffffffffu, c0, o);
                c1 += __shfl_xor_sync(0xffffffffu, c1, o);
            }
            if (g == 0) {
                const int col0 = n0 + n_base + 8 * nt + 2 * tg;
                atomicAdd(&g_csum[z * 2048 + col0],     c0);
                atomicAdd(&g_csum[z * 2048 + col0 + 1], c1);
            }
        }
        __syncthreads();
        // E^T (fp16): warp handles 4 j-rows, 8B coalesced stores along i
        __half* CT = g_st + (size_t)z * NLA * NLB;
        const int jrow = warp * 4 + (lane >> 3);
        const int iofs = (lane & 7) * 4;
        for (int jj = jrow; jj < 128; jj += 32) {
            #pragma unroll
            for (int i0 = iofs; i0 < 128; i0 += 32) {
                float4 v;
                v.x = tile[(i0 + 0) * 129 + jj];
                v.y = tile[(i0 + 1) * 129 + jj];
                v.z = tile[(i0 + 2) * 129 + jj];
                v.w = tile[(i0 + 3) * 129 + jj];
                uint2 st = make_uint2(pack_h2(v.x, v.y), pack_h2(v.z, v.w));
                *(uint2*)(CT + (size_t)(n0 + jj) * 2048 + m0 + i0) = st;
            }
        }
    } else if (MODE == 0) {
        #pragma unroll
        for (int mt = 0; mt < 4; ++mt) {
            const int row0 = m0 + m_base + 16 * mt + g;
            #pragma unroll
            for (int nt = 0; nt < 4; ++nt) {
                const int col0 = n0 + n_base + 8 * nt + 2 * tg;
                const float2 bv = *(const float2*)(aux + col0);
                *(__half2*)(Ch + (size_t)row0 * 512 + col0) =
                    __floats2half2_rn(acc[mt][nt][0] + bv.x, acc[mt][nt][1] + bv.y);
                *(__half2*)(Ch + (size_t)(row0 + 8) * 512 + col0) =
                    __floats2half2_rn(acc[mt][nt][2] + bv.x, acc[mt][nt][3] + bv.y);
            }
        }
    } else {
        #pragma unroll
        for (int mt = 0; mt < 4; ++mt) {
            const int row0 = m0 + m_base + 16 * mt + g;
            #pragma unroll
            for (int nt = 0; nt < 4; ++nt) {
                const int col0 = n0 + n_base + 8 * nt + 2 * tg;
                const float2 e0 = *(const float2*)(aux + (size_t)row0 * 512 + col0);
                const float2 e1 = *(const float2*)(aux + (size_t)(row0 + 8) * 512 + col0);
                *(float2*)(Cf + (size_t)row0 * 512 + col0) =
                    make_float2(acc[mt][nt][0] + e0.x, acc[mt][nt][1] + e0.y);
                *(float2*)(Cf + (size_t)(row0 + 8) * 512 + col0) =
                    make_float2(acc[mt][nt][2] + e1.x, acc[mt][nt][3] + e1.y);
            }
        }
    }
}

// ---------------------------------------------------------------------------
template <int DSTSEL>
__global__ void __launch_bounds__(256) transpose_k(const float* __restrict__ src,
                                                   int R, int C)
{
    __shared__ float tile[32][33];
    __half* dstbase = (DSTSEL == 0) ? g_wat : (DSTSEL == 1) ? g_wbt
                    : (DSTSEL == 2) ? g_iat : g_ibt;
    const int z = blockIdx.z;
    const float* s = src + (size_t)z * R * C;
    __half* d = dstbase + (size_t)z * R * C;

    int x = blockIdx.x * 32 + threadIdx.x;
    int y = blockIdx.y * 32 + threadIdx.y;
    #pragma unroll
    for (int j = 0; j < 32; j += 8)
        tile[threadIdx.y + j][threadIdx.x] = s[(size_t)(y + j) * C + x];
    __syncthreads();
    x = blockIdx.y * 32 + threadIdx.x;
    y = blockIdx.x * 32 + threadIdx.y;
    #pragma unroll
    for (int j = 0; j < 32; j += 8)
        d[(size_t)(y + j) * R + x] = __float2half(tile[threadIdx.x][threadIdx.y + j]);
}

// ---------------------------------------------------------------------------
__global__ void __launch_bounds__(256) zero_k()
{
    const int i = blockIdx.x * 256 + threadIdx.x;
    g_rsum[i] = 0.f;
    g_csum[i] = 0.f;
}
__global__ void __launch_bounds__(256) recip_k()
{
    const int i = blockIdx.x * 256 + threadIdx.x;
    g_rinv[i] = 1.f / g_rsum[i];
    g_cinv[i] = 1.f / g_csum[i];
}

// ---------------------------------------------------------------------------
extern "C" void kernel_launch(void* const* d_in, const int* in_sizes, int n_in,
                              void* d_out, int out_size)
{
    (void)in_sizes; (void)n_in; (void)out_size;
    const float* input_a = (const float*)d_in[0];
    const float* input_b = (const float*)d_in[1];
    const int*   mask_a  = (const int*)d_in[2];
    const int*   mask_b  = (const int*)d_in[3];
    const float* Wa      = (const float*)d_in[4];
    const float* ba      = (const float*)d_in[5];
    const float* Wb      = (const float*)d_in[6];
    const float* bb      = (const float*)d_in[7];
    float* out = (float*)d_out;

    static bool attr_done = false;
    if (!attr_done) {
        cudaFuncSetAttribute(tc_gemm<0,0>, cudaFuncAttributeMaxDynamicSharedMemorySize, PIPE_SMEM);
        cudaFuncSetAttribute(tc_gemm<0,1>, cudaFuncAttributeMaxDynamicSharedMemorySize, PIPE_SMEM);
        cudaFuncSetAttribute(tc_gemm<1,0>, cudaFuncAttributeMaxDynamicSharedMemorySize, TILE_SMEM);
        cudaFuncSetAttribute(tc_gemm<2,0>, cudaFuncAttributeMaxDynamicSharedMemorySize, PIPE_SMEM);
        cudaFuncSetAttribute(tc_gemm<3,0>, cudaFuncAttributeMaxDynamicSharedMemorySize, PIPE_SMEM);
        attr_done = true;
    }

    // zero fused-sum accumulators (graph replays re-run this)
    zero_k<<<NB * 2048 / 256, 256>>>();

    // transposes (fp32 -> fp16): W^T and input^T
    transpose_k<0><<<dim3(16, 16, 1),  dim3(32, 8)>>>(Wa, 512, 512);
    transpose_k<1><<<dim3(16, 16, 1),  dim3(32, 8)>>>(Wb, 512, 512);
    transpose_k<2><<<dim3(16, 64, NB), dim3(32, 8)>>>(input_a, 2048, 512);
    transpose_k<3><<<dim3(16, 64, NB), dim3(32, 8)>>>(input_b, 2048, 512);

    // projections -> fp16 mapped
    tc_gemm<0,0><<<dim3(4, 128, 1), 256, PIPE_SMEM>>>(input_a, ba, nullptr, nullptr, nullptr);
    tc_gemm<0,1><<<dim3(4, 128, 1), 256, PIPE_SMEM>>>(input_b, bb, nullptr, nullptr, nullptr);

    // masked exp-scores -> g_s, g_st (fp16) + fused row/col sums
    tc_gemm<1,0><<<dim3(16, 16, NB), 256, TILE_SMEM>>>(nullptr, nullptr, mask_a, mask_b, nullptr);

    // denominators -> reciprocals
    recip_k<<<NB * 2048 / 256, 256>>>();

    // attention-weighted outputs + residual
    tc_gemm<2,0><<<dim3(4, 16, NB), 256, PIPE_SMEM>>>(nullptr, input_a, nullptr, nullptr, out);
    tc_gemm<3,0><<<dim3(4, 16, NB), 256, PIPE_SMEM>>>(nullptr, input_b, nullptr, nullptr,
                                                      out + (size_t)NB * NLA * ND);
}

// round 6
// speedup vs baseline: 6.7689x; 1.4658x over previous
#include <cuda_runtime.h>
#include <cuda_fp16.h>
#include <cstdint>

// ---------------------------------------------------------------------------
// CrossAttention, fp16 dataflow + cp.async producers + ldmatrix consumers.
//   prep: fp32 inputs -> fp16 copies + fp16 transposes
//   proj -> E=exp(scale*s) fp16 + E^T fp16 + fused sums -> recip
//   -> pre-scale B operands by inv sums -> AV GEMMs (fp32 out + residual)
// ---------------------------------------------------------------------------

namespace {
constexpr int NB = 8, NLA = 2048, NLB = 2048, ND = 512, NH = 512;
constexpr float SCALE = 0.04419417382415922f;   // 1/sqrt(512)
constexpr float EXPM  = 1e-6f;                   // masked-entry E value

constexpr int BM = 128, BN = 128, BK = 32;       // chunk = 2 k16 steps
constexpr int ROWB = 80;                          // smem row pitch (bytes) = 40 halfs
constexpr int OP_BYTES = BM * ROWB;               // 10240 per operand per stage
constexpr int STAGE_BYTES = 2 * OP_BYTES;         // 20480
constexpr int NSTG = 4;
constexpr int DYN_SMEM = NSTG * STAGE_BYTES;      // 81920 (>= 66048 epilogue tile)
}

// ---- scratch ----------------------------------------------------------------
__device__ __half g_wat[512 * 512];
__device__ __half g_wbt[512 * 512];
__device__ __half g_iha[NB * 2048 * 512];         // fp16 input_a (row-major)
__device__ __half g_ihb[NB * 2048 * 512];         // fp16 input_b
__device__ __half g_iat[NB * 512 * 2048];         // fp16 input_a^T (later *rinv)
__device__ __half g_ibt[NB * 512 * 2048];         // fp16 input_b^T (later *cinv)
__device__ __half g_ma[NB * NLA * NH];
__device__ __half g_mb[NB * NLB * NH];
__device__ __half g_s [(size_t)NB * NLA * NLB];   // E[i][j]
__device__ __half g_st[(size_t)NB * NLA * NLB];   // E^T[j][i]
__device__ float g_rsum[NB * NLA];
__device__ float g_csum[NB * NLB];
__device__ float g_rinv[NB * NLA];
__device__ float g_cinv[NB * NLB];

// ---- helpers ------------------------------------------------------------------
__device__ __forceinline__ uint32_t smem_u32(const void* p) {
    uint32_t a;
    asm("{ .reg .u64 t; cvta.to.shared.u64 t, %1; cvt.u32.u64 %0, t; }"
        : "=r"(a) : "l"(p));
    return a;
}
__device__ __forceinline__ void cpa16(uint32_t s, const void* g) {
    asm volatile("cp.async.cg.shared.global [%0], [%1], 16;" :: "r"(s), "l"(g));
}
__device__ __forceinline__ void cpa_commit() {
    asm volatile("cp.async.commit_group;" ::: "memory");
}
__device__ __forceinline__ void cpa_wait2() {
    asm volatile("cp.async.wait_group 2;" ::: "memory");
}
__device__ __forceinline__ void ldm4(uint32_t (&r)[4], uint32_t a) {
    asm volatile("ldmatrix.sync.aligned.m8n8.x4.shared.b16 {%0,%1,%2,%3}, [%4];"
                 : "=r"(r[0]), "=r"(r[1]), "=r"(r[2]), "=r"(r[3]) : "r"(a));
}
__device__ __forceinline__ void mma_f16(float (&d)[4],
                                        uint32_t a0, uint32_t a1, uint32_t a2, uint32_t a3,
                                        uint32_t b0, uint32_t b1) {
    asm volatile(
        "mma.sync.aligned.m16n8k16.row.col.f32.f16.f16.f32 "
        "{%0,%1,%2,%3}, {%4,%5,%6,%7}, {%8,%9}, {%0,%1,%2,%3};"
        : "+f"(d[0]), "+f"(d[1]), "+f"(d[2]), "+f"(d[3])
        : "r"(a0), "r"(a1), "r"(a2), "r"(a3), "r"(b0), "r"(b1));
}
__device__ __forceinline__ uint32_t pack_h2(float x, float y) {
    __half2 h = __floats2half2_rn(x, y);
    return *reinterpret_cast<uint32_t*>(&h);
}

// ---------------------------------------------------------------------------
// fp16 GEMM, all operands fp16 in gmem, cp.async 4-stage pipeline, ldmatrix.
// MODE 0: proj (WHICH 0: iha@wat -> g_ma, 1: ihb@wbt -> g_mb), epi bias fp32
// MODE 1: scores: E = exp(scale * ma.mb^T), masked->EXPM; g_s, g_st, fused sums
// MODE 2: out_a = E @ ibt_scaled + resid input_a (fp32)
// MODE 3: out_b = E^T @ iat_scaled + resid input_b (fp32)
// ---------------------------------------------------------------------------
template <int MODE, int WHICH>
__global__ void __launch_bounds__(256, 2)
tc_gemm(const float* __restrict__ X2,
        const int* __restrict__ MR, const int* __restrict__ MCm,
        float* __restrict__ OUT)
{
    constexpr int K   = (MODE <= 1) ? 512 : 2048;
    constexpr int NC  = K / BK;
    constexpr int LDA = (MODE >= 2) ? 2048 : 512;
    constexpr int LDB = (MODE >= 2) ? 2048 : 512;

    extern __shared__ __align__(16) char smem_raw[];
    const uint32_t smb = smem_u32(smem_raw);

    const int tid = threadIdx.x;
    const int z   = blockIdx.z;
    const int m0  = blockIdx.y * BM;
    const int n0  = blockIdx.x * BN;

    // ---- mode pointers (all fp16 operands) ----
    const __half* Ah; const __half* Bh;
    const float* aux = nullptr;
    __half* Ch = nullptr; float* Cf = nullptr;
    if (MODE == 0) {
        Ah = WHICH ? g_ihb : g_iha;
        Bh = WHICH ? g_wbt : g_wat;
        Ch = WHICH ? g_mb : g_ma; aux = X2;
    } else if (MODE == 1) {
        Ah = g_ma + (size_t)z * 2048 * 512;
        Bh = g_mb + (size_t)z * 2048 * 512;
        Ch = g_s  + (size_t)z * NLA * NLB;
    } else if (MODE == 2) {
        Ah = g_s   + (size_t)z * NLA * NLB;
        Bh = g_ibt + (size_t)z * ND * NLB;
        Cf = OUT   + (size_t)z * NLA * ND;
        aux = X2   + (size_t)z * NLA * ND;
    } else {
        Ah = g_st  + (size_t)z * NLA * NLB;
        Bh = g_iat + (size_t)z * ND * NLA;
        Cf = OUT   + (size_t)z * NLB * ND;
        aux = X2   + (size_t)z * NLB * ND;
    }

    // ---- producer: 4 x cp.async(16B) per thread per chunk ----
    const int prow = tid >> 1;             // 0..127
    const int pgrp = (tid & 1) * 2;        // 16B-group 0/2 (and +1)
    const uint32_t soff = (uint32_t)(prow * ROWB + pgrp * 16);
    const __half* gA = Ah + (size_t)(m0 + prow) * LDA + pgrp * 8;
    const __half* gB = Bh + (size_t)(n0 + prow) * LDB + pgrp * 8;

    auto issueChunk = [&](int c, int st) {
        const uint32_t sa = smb + st * STAGE_BYTES + soff;
        const __half* ga = gA + c * BK;
        const __half* gb = gB + c * BK;
        cpa16(sa, ga);
        cpa16(sa + 16, ga + 8);
        cpa16(sa + OP_BYTES, gb);
        cpa16(sa + OP_BYTES + 16, gb + 8);
    };

    // ---- consumer identity ----
    const int warp = tid >> 5, lane = tid & 31;
    const int wm = warp >> 2, wn = warp & 3;       // 2 x 4 warp grid
    const int m_base = wm * 64, n_base = wn * 32;
    const int g = lane >> 2, tg = lane & 3;

    // ldmatrix lane address components (within tile, bytes)
    const uint32_t a_row = (uint32_t)(m_base + (lane & 15)) * ROWB + (lane >> 4) * 16;
    const uint32_t b_row = (uint32_t)(n_base + ((lane >> 4) << 3) + (lane & 7)) * ROWB
                         + ((lane >> 3) & 1) * 16;

    float acc[4][4][4] = {};

    #pragma unroll
    for (int c = 0; c < 3; ++c) { issueChunk(c, c); cpa_commit(); }

    for (int c = 0; c < NC; ++c) {
        cpa_wait2();
        __syncthreads();
        const uint32_t ab = smb + (c & 3) * STAGE_BYTES;
        const uint32_t bb = ab + OP_BYTES;
        #pragma unroll
        for (int s = 0; s < 2; ++s) {
            uint32_t af[4][4], bq[2][4];
            #pragma unroll
            for (int mt = 0; mt < 4; ++mt)
                ldm4(af[mt], ab + a_row + mt * (16 * ROWB) + s * 32);
            #pragma unroll
            for (int np = 0; np < 2; ++np)
                ldm4(bq[np], bb + b_row + np * (16 * ROWB) + s * 32);
            #pragma unroll
            for (int mt = 0; mt < 4; ++mt)
                #pragma unroll
                for (int nt = 0; nt < 4; ++nt)
                    mma_f16(acc[mt][nt],
                            af[mt][0], af[mt][1], af[mt][2], af[mt][3],
                            bq[nt >> 1][(nt & 1) * 2], bq[nt >> 1][(nt & 1) * 2 + 1]);
        }
        if (c + 3 < NC) issueChunk(c + 3, (c + 3) & 3);
        cpa_commit();
    }
    __syncthreads();

    // ---- epilogue ----
    if (MODE == 1) {
        float* tile = (float*)smem_raw;            // [128][129]
        float csum0[4] = {0.f, 0.f, 0.f, 0.f};
        float csum1[4] = {0.f, 0.f, 0.f, 0.f};
        #pragma unroll
        for (int mt = 0; mt < 4; ++mt) {
            const int row0 = m0 + m_base + 16 * mt + g;
            const int rm0 = MR[z * 2048 + row0];
            const int rm1 = MR[z * 2048 + row0 + 8];
            float rsum0 = 0.f, rsum1 = 0.f;
            #pragma unroll
            for (int nt = 0; nt < 4; ++nt) {
                const int col0 = n0 + n_base + 8 * nt + 2 * tg;
                const int2 cm = *(const int2*)&MCm[z * 2048 + col0];
                float e00 = (rm0 * cm.x == 0) ? EXPM : __expf(acc[mt][nt][0] * SCALE);
                float e01 = (rm0 * cm.y == 0) ? EXPM : __expf(acc[mt][nt][1] * SCALE);
                float e10 = (rm1 * cm.x == 0) ? EXPM : __expf(acc[mt][nt][2] * SCALE);
                float e11 = (rm1 * cm.y == 0) ? EXPM : __expf(acc[mt][nt][3] * SCALE);
                __half2 p0 = __floats2half2_rn(e00, e01);
                __half2 p1 = __floats2half2_rn(e10, e11);
                *(__half2*)(Ch + (size_t)row0 * 2048 + col0)       = p0;
                *(__half2*)(Ch + (size_t)(row0 + 8) * 2048 + col0) = p1;
                float2 r0 = __half22float2(p0);
                float2 r1 = __half22float2(p1);
                const int li = m_base + 16 * mt + g;
                const int lj = n_base + 8 * nt + 2 * tg;
                tile[li * 129 + lj]           = r0.x;
                tile[li * 129 + lj + 1]       = r0.y;
                tile[(li + 8) * 129 + lj]     = r1.x;
                tile[(li + 8) * 129 + lj + 1] = r1.y;
                rsum0 += r0.x + r0.y;
                rsum1 += r1.x + r1.y;
                csum0[nt] += r0.x + r1.x;
                csum1[nt] += r0.y + r1.y;
            }
            rsum0 += __shfl_xor_sync(0xffffffffu, rsum0, 1);
            rsum0 += __shfl_xor_sync(0xffffffffu, rsum0, 2);
            rsum1 += __shfl_xor_sync(0xffffffffu, rsum1, 1);
            rsum1 += __shfl_xor_sync(0xffffffffu, rsum1, 2);
            if (tg == 0) {
                atomicAdd(&g_rsum[z * 2048 + row0],     rsum0);
                atomicAdd(&g_rsum[z * 2048 + row0 + 8], rsum1);
            }
        }
        #pragma unroll
        for (int nt = 0; nt < 4; ++nt) {
            float c0 = csum0[nt], c1 = csum1[nt];
            #pragma unroll
            for (int o = 4; o <= 16; o <<= 1) {
                c0 += __shfl_xor_sync(0xffffffffu, c0, o);
                c1 += __shfl_xor_sync(0xffffffffu, c1, o);
            }
            if (g == 0) {
                const int col0 = n0 + n_base + 8 * nt + 2 * tg;
                atomicAdd(&g_csum[z * 2048 + col0],     c0);
                atomicAdd(&g_csum[z * 2048 + col0 + 1], c1);
            }
        }
        __syncthreads();
        __half* CT = g_st + (size_t)z * NLA * NLB;
        const int jrow = warp * 4 + (lane >> 3);
        const int iofs = (lane & 7) * 4;
        for (int jj = jrow; jj < 128; jj += 32) {
            #pragma unroll
            for (int i0 = iofs; i0 < 128; i0 += 32) {
                float4 v;
                v.x = tile[(i0 + 0) * 129 + jj];
                v.y = tile[(i0 + 1) * 129 + jj];
                v.z = tile[(i0 + 2) * 129 + jj];
                v.w = tile[(i0 + 3) * 129 + jj];
                uint2 st = make_uint2(pack_h2(v.x, v.y), pack_h2(v.z, v.w));
                *(uint2*)(CT + (size_t)(n0 + jj) * 2048 + m0 + i0) = st;
            }
        }
    } else if (MODE == 0) {
        #pragma unroll
        for (int mt = 0; mt < 4; ++mt) {
            const int row0 = m0 + m_base + 16 * mt + g;
            #pragma unroll
            for (int nt = 0; nt < 4; ++nt) {
                const int col0 = n0 + n_base + 8 * nt + 2 * tg;
                const float2 bv = *(const float2*)(aux + col0);
                *(__half2*)(Ch + (size_t)row0 * 512 + col0) =
                    __floats2half2_rn(acc[mt][nt][0] + bv.x, acc[mt][nt][1] + bv.y);
                *(__half2*)(Ch + (size_t)(row0 + 8) * 512 + col0) =
                    __floats2half2_rn(acc[mt][nt][2] + bv.x, acc[mt][nt][3] + bv.y);
            }
        }
    } else {
        #pragma unroll
        for (int mt = 0; mt < 4; ++mt) {
            const int row0 = m0 + m_base + 16 * mt + g;
            #pragma unroll
            for (int nt = 0; nt < 4; ++nt) {
                const int col0 = n0 + n_base + 8 * nt + 2 * tg;
                const float2 e0 = *(const float2*)(aux + (size_t)row0 * 512 + col0);
                const float2 e1 = *(const float2*)(aux + (size_t)(row0 + 8) * 512 + col0);
                *(float2*)(Cf + (size_t)row0 * 512 + col0) =
                    make_float2(acc[mt][nt][0] + e0.x, acc[mt][nt][1] + e0.y);
                *(float2*)(Cf + (size_t)(row0 + 8) * 512 + col0) =
                    make_float2(acc[mt][nt][2] + e1.x, acc[mt][nt][3] + e1.y);
            }
        }
    }
}

// ---------------------------------------------------------------------------
// prep: fp32 src -> fp16 transpose (always) + fp16 straight copy (COPY=1)
// DSTSEL: 0 wat, 1 wbt, 2 iat(+iha), 3 ibt(+ihb)
// ---------------------------------------------------------------------------
template <int DSTSEL>
__global__ void __launch_bounds__(256) prep_k(const float* __restrict__ src,
                                              int R, int C)
{
    __shared__ float tile[32][33];
    __half* tbase = (DSTSEL == 0) ? g_wat : (DSTSEL == 1) ? g_wbt
                  : (DSTSEL == 2) ? g_iat : g_ibt;
    __half* cbase = (DSTSEL == 2) ? g_iha : (DSTSEL == 3) ? g_ihb : nullptr;
    const int z = blockIdx.z;
    const float* s = src + (size_t)z * R * C;
    __half* d = tbase + (size_t)z * R * C;

    int x = blockIdx.x * 32 + threadIdx.x;
    int y = blockIdx.y * 32 + threadIdx.y;
    #pragma unroll
    for (int j = 0; j < 32; j += 8) {
        float v = s[(size_t)(y + j) * C + x];
        tile[threadIdx.y + j][threadIdx.x] = v;
        if (DSTSEL >= 2)
            (cbase + (size_t)z * R * C)[(size_t)(y + j) * C + x] = __float2half(v);
    }
    __syncthreads();
    x = blockIdx.y * 32 + threadIdx.x;
    y = blockIdx.x * 32 + threadIdx.y;
    #pragma unroll
    for (int j = 0; j < 32; j += 8)
        d[(size_t)(y + j) * R + x] = __float2half(tile[threadIdx.x][threadIdx.y + j]);
}

// ---------------------------------------------------------------------------
__global__ void __launch_bounds__(256) zero_k()
{
    const int i = blockIdx.x * 256 + threadIdx.x;
    g_rsum[i] = 0.f;
    g_csum[i] = 0.f;
}
__global__ void __launch_bounds__(256) recip_k()
{
    const int i = blockIdx.x * 256 + threadIdx.x;
    g_rinv[i] = 1.f / g_rsum[i];
    g_cinv[i] = 1.f / g_csum[i];
}
// scale g_ibt rows by cinv (y=0) / g_iat rows by rinv (y=1); 8 halfs per thread
__global__ void __launch_bounds__(256) scaleb_k()
{
    const int idx = blockIdx.x * 256 + threadIdx.x;     // 0 .. 512*256-1
    const int z = blockIdx.z;
    const int d = idx >> 8;
    const int j8 = (idx & 255) * 8;
    __half* base = (blockIdx.y ? g_iat : g_ibt) + (size_t)z * 512 * 2048 + (size_t)d * 2048 + j8;
    const float* inv = (blockIdx.y ? g_rinv : g_cinv) + z * 2048 + j8;
    uint4 v = *(uint4*)base;
    __half2* hp = (__half2*)&v;
    #pragma unroll
    for (int q = 0; q < 4; ++q) {
        float2 f = __half22float2(hp[q]);
        f.x *= inv[2 * q];
        f.y *= inv[2 * q + 1];
        hp[q] = __floats2half2_rn(f.x, f.y);
    }
    *(uint4*)base = v;
}

// ---------------------------------------------------------------------------
extern "C" void kernel_launch(void* const* d_in, const int* in_sizes, int n_in,
                              void* d_out, int out_size)
{
    (void)in_sizes; (void)n_in; (void)out_size;
    const float* input_a = (const float*)d_in[0];
    const float* input_b = (const float*)d_in[1];
    const int*   mask_a  = (const int*)d_in[2];
    const int*   mask_b  = (const int*)d_in[3];
    const float* Wa      = (const float*)d_in[4];
    const float* ba      = (const float*)d_in[5];
    const float* Wb      = (const float*)d_in[6];
    const float* bb      = (const float*)d_in[7];
    float* out = (float*)d_out;

    static bool attr_done = false;
    if (!attr_done) {
        cudaFuncSetAttribute(tc_gemm<0,0>, cudaFuncAttributeMaxDynamicSharedMemorySize, DYN_SMEM);
        cudaFuncSetAttribute(tc_gemm<0,1>, cudaFuncAttributeMaxDynamicSharedMemorySize, DYN_SMEM);
        cudaFuncSetAttribute(tc_gemm<1,0>, cudaFuncAttributeMaxDynamicSharedMemorySize, DYN_SMEM);
        cudaFuncSetAttribute(tc_gemm<2,0>, cudaFuncAttributeMaxDynamicSharedMemorySize, DYN_SMEM);
        cudaFuncSetAttribute(tc_gemm<3,0>, cudaFuncAttributeMaxDynamicSharedMemorySize, DYN_SMEM);
        attr_done = true;
    }

    zero_k<<<NB * 2048 / 256, 256>>>();

    // prep: fp16 transposes + fp16 input copies
    prep_k<0><<<dim3(16, 16, 1),  dim3(32, 8)>>>(Wa, 512, 512);
    prep_k<1><<<dim3(16, 16, 1),  dim3(32, 8)>>>(Wb, 512, 512);
    prep_k<2><<<dim3(16, 64, NB), dim3(32, 8)>>>(input_a, 2048, 512);
    prep_k<3><<<dim3(16, 64, NB), dim3(32, 8)>>>(input_b, 2048, 512);

    // projections -> fp16 mapped
    tc_gemm<0,0><<<dim3(4, 128, 1), 256, DYN_SMEM>>>(ba, nullptr, nullptr, nullptr);
    tc_gemm<0,1><<<dim3(4, 128, 1), 256, DYN_SMEM>>>(bb, nullptr, nullptr, nullptr);

    // masked exp-scores -> g_s, g_st (fp16) + fused row/col sums
    tc_gemm<1,0><<<dim3(16, 16, NB), 256, DYN_SMEM>>>(nullptr, mask_a, mask_b, nullptr);

    // denominators -> reciprocals, then fold into B operands
    recip_k<<<NB * 2048 / 256, 256>>>();
    scaleb_k<<<dim3(512, 2, NB), 256>>>();

    // attention-weighted outputs + residual
    tc_gemm<2,0><<<dim3(4, 16, NB), 256, DYN_SMEM>>>(input_a, nullptr, nullptr, out);
    tc_gemm<3,0><<<dim3(4, 16, NB), 256, DYN_SMEM>>>(input_b, nullptr, nullptr,
                                                     out + (size_t)NB * NLA * ND);
}

// round 7
// speedup vs baseline: 7.2165x; 1.0661x over previous
#include <cuda_runtime.h>
#include <cuda_fp16.h>
#include <cstdint>

// ---------------------------------------------------------------------------
// CrossAttention, fp16 dataflow, cp.async + ldmatrix(+trans) mma.sync GEMMs.
//   prep: fp32 inputs -> fp16 copies + fp16 transposes (+zero sums)
//   proj -> E=exp(scale*s) fp16 (single copy!) + fused row/col sums -> recip
//   -> pre-scale B operands -> out_a (E @ ibt), out_b (E^T @ iat via ldmatrix.trans)
// ---------------------------------------------------------------------------

namespace {
constexpr int NB = 8, NLA = 2048, NLB = 2048, ND = 512, NH = 512;
constexpr float SCALE = 0.04419417382415922f;   // 1/sqrt(512)
constexpr float EXPM  = 1e-6f;                   // masked-entry E value

constexpr int BM = 128, BN = 128, BK = 32;       // chunk = 2 k16 steps
constexpr int ROWB = 80;                          // standard operand row pitch (bytes)
constexpr int OPB_STD = BM * ROWB;                // 10240
// MODE 3 A operand: 32 i-rows x 256B (128 j-halfs), pitch 272
constexpr int APITCH_T = 272;
constexpr int OPB_TRA = 32 * APITCH_T;            // 8704
constexpr int NSTG = 4;
constexpr int DYN_SMEM = NSTG * 2 * OPB_STD;      // 81920 (max over modes)
}

// ---- scratch ----------------------------------------------------------------
__device__ __half g_wat[512 * 512];
__device__ __half g_wbt[512 * 512];
__device__ __half g_iha[NB * 2048 * 512];         // fp16 input_a (row-major)
__device__ __half g_ihb[NB * 2048 * 512];         // fp16 input_b
__device__ __half g_iat[NB * 512 * 2048];         // fp16 input_a^T (later *rinv)
__device__ __half g_ibt[NB * 512 * 2048];         // fp16 input_b^T (later *cinv)
__device__ __half g_ma[NB * NLA * NH];
__device__ __half g_mb[NB * NLB * NH];
__device__ __half g_s [(size_t)NB * NLA * NLB];   // E[i][j]
__device__ float g_rsum[NB * NLA];
__device__ float g_csum[NB * NLB];
__device__ float g_rinv[NB * NLA];
__device__ float g_cinv[NB * NLB];

// ---- helpers ------------------------------------------------------------------
__device__ __forceinline__ uint32_t smem_u32(const void* p) {
    uint32_t a;
    asm("{ .reg .u64 t; cvta.to.shared.u64 t, %1; cvt.u32.u64 %0, t; }"
        : "=r"(a) : "l"(p));
    return a;
}
__device__ __forceinline__ void cpa16(uint32_t s, const void* g) {
    asm volatile("cp.async.cg.shared.global [%0], [%1], 16;" :: "r"(s), "l"(g));
}
__device__ __forceinline__ void cpa_commit() {
    asm volatile("cp.async.commit_group;" ::: "memory");
}
__device__ __forceinline__ void cpa_wait2() {
    asm volatile("cp.async.wait_group 2;" ::: "memory");
}
__device__ __forceinline__ void ldm4(uint32_t (&r)[4], uint32_t a) {
    asm volatile("ldmatrix.sync.aligned.m8n8.x4.shared.b16 {%0,%1,%2,%3}, [%4];"
                 : "=r"(r[0]), "=r"(r[1]), "=r"(r[2]), "=r"(r[3]) : "r"(a));
}
__device__ __forceinline__ void ldm4t(uint32_t (&r)[4], uint32_t a) {
    asm volatile("ldmatrix.sync.aligned.m8n8.x4.trans.shared.b16 {%0,%1,%2,%3}, [%4];"
                 : "=r"(r[0]), "=r"(r[1]), "=r"(r[2]), "=r"(r[3]) : "r"(a));
}
__device__ __forceinline__ void mma_f16(float (&d)[4],
                                        uint32_t a0, uint32_t a1, uint32_t a2, uint32_t a3,
                                        uint32_t b0, uint32_t b1) {
    asm volatile(
        "mma.sync.aligned.m16n8k16.row.col.f32.f16.f16.f32 "
        "{%0,%1,%2,%3}, {%4,%5,%6,%7}, {%8,%9}, {%0,%1,%2,%3};"
        : "+f"(d[0]), "+f"(d[1]), "+f"(d[2]), "+f"(d[3])
        : "r"(a0), "r"(a1), "r"(a2), "r"(a3), "r"(b0), "r"(b1));
}

// ---------------------------------------------------------------------------
// fp16 GEMM, cp.async 4-stage pipeline, ldmatrix consumers.
// MODE 0: proj (WHICH 0: iha@wat -> g_ma, 1: ihb@wbt -> g_mb), epi bias fp32
// MODE 1: scores: E = exp(scale * ma.mb^T), masked->EXPM; writes g_s + fused sums
// MODE 2: out_a = E @ ibt_scaled + resid input_a (fp32)
// MODE 3: out_b = E^T @ iat_scaled + resid input_b (A via ldmatrix.trans on E)
// ---------------------------------------------------------------------------
template <int MODE, int WHICH>
__global__ void __launch_bounds__(256, 2)
tc_gemm(const float* __restrict__ X2,
        const int* __restrict__ MR, const int* __restrict__ MCm,
        float* __restrict__ OUT)
{
    constexpr bool TRA = (MODE == 3);
    constexpr int K   = (MODE <= 1) ? 512 : 2048;
    constexpr int NC  = K / BK;
    constexpr int LDA = (MODE >= 2) ? 2048 : 512;
    constexpr int LDB = (MODE >= 2) ? 2048 : 512;
    constexpr int OPB_A   = TRA ? OPB_TRA : OPB_STD;          // A bytes per stage
    constexpr int STG_B   = OPB_A + OPB_STD;                  // stage bytes

    extern __shared__ __align__(16) char smem_raw[];
    const uint32_t smb = smem_u32(smem_raw);

    const int tid = threadIdx.x;
    const int z   = blockIdx.z;
    const int m0  = blockIdx.y * BM;
    const int n0  = blockIdx.x * BN;

    // ---- mode pointers (all fp16 operands) ----
    const __half* Ah; const __half* Bh;
    const float* aux = nullptr;
    __half* Ch = nullptr; float* Cf = nullptr;
    if (MODE == 0) {
        Ah = WHICH ? g_ihb : g_iha;
        Bh = WHICH ? g_wbt : g_wat;
        Ch = WHICH ? g_mb : g_ma; aux = X2;
    } else if (MODE == 1) {
        Ah = g_ma + (size_t)z * 2048 * 512;
        Bh = g_mb + (size_t)z * 2048 * 512;
        Ch = g_s  + (size_t)z * NLA * NLB;
    } else if (MODE == 2) {
        Ah = g_s   + (size_t)z * NLA * NLB;
        Bh = g_ibt + (size_t)z * ND * NLB;
        Cf = OUT   + (size_t)z * NLA * ND;
        aux = X2   + (size_t)z * NLA * ND;
    } else {
        Ah = g_s   + (size_t)z * NLA * NLB;   // E, read transposed (m0 = j offset)
        Bh = g_iat + (size_t)z * ND * NLA;
        Cf = OUT   + (size_t)z * NLB * ND;
        aux = X2   + (size_t)z * NLB * ND;
    }

    // ---- producer geometry ----
    // standard A / all B: thread -> (row = tid>>1, 2x16B at (tid&1)*32 bytes)
    const int prow = tid >> 1;
    const int pgrp = (tid & 1) * 2;
    const uint32_t soffB = (uint32_t)(prow * ROWB + pgrp * 16);
    const __half* gB = Bh + (size_t)(n0 + prow) * LDB + pgrp * 8;
    // trans A (MODE 3): thread -> (i-row = tid>>3, 2x16B at (tid&7)*32 bytes)
    const int tarow = tid >> 3;
    const int tacol = (tid & 7) * 16;               // halfs
    const uint32_t soffAT = (uint32_t)(tarow * APITCH_T + tacol * 2);
    // standard A gmem base
    const __half* gA_std = Ah + (size_t)(m0 + prow) * LDA + pgrp * 8;
    // trans A gmem base: row i = c*BK + tarow, col j = m0 + tacol
    const __half* gA_tra = Ah + m0 + tacol;

    auto issueChunk = [&](int c, int st) {
        const uint32_t sbase = smb + st * STG_B;
        if (TRA) {
            const __half* ga = gA_tra + (size_t)(c * BK + tarow) * 2048;
            cpa16(sbase + soffAT, ga);
            cpa16(sbase + soffAT + 16, ga + 8);
        } else {
            const uint32_t sa = sbase + (uint32_t)(prow * ROWB + pgrp * 16);
            const __half* ga = gA_std + c * BK;
            cpa16(sa, ga);
            cpa16(sa + 16, ga + 8);
        }
        const uint32_t sb = sbase + OPB_A + soffB;
        const __half* gb = gB + c * BK;
        cpa16(sb, gb);
        cpa16(sb + 16, gb + 8);
    };

    // ---- consumer identity ----
    const int warp = tid >> 5, lane = tid & 31;
    const int wm = warp >> 2, wn = warp & 3;       // 2 x 4 warp grid
    const int m_base = wm * 64, n_base = wn * 32;
    const int g = lane >> 2, tg = lane & 3;

    // ldmatrix lane addresses (bytes within tile)
    const uint32_t a_row = (uint32_t)(m_base + (lane & 15)) * ROWB + (lane >> 4) * 16;
    const uint32_t a_row_t = (uint32_t)((lane >> 4) * 8 + (lane & 7)) * APITCH_T
                           + ((lane >> 3) & 1) * 16 + (uint32_t)m_base * 2;
    const uint32_t b_row = (uint32_t)(n_base + ((lane >> 4) << 3) + (lane & 7)) * ROWB
                         + ((lane >> 3) & 1) * 16;

    float acc[4][4][4] = {};

    #pragma unroll
    for (int c = 0; c < 3; ++c) { issueChunk(c, c); cpa_commit(); }

    for (int c = 0; c < NC; ++c) {
        cpa_wait2();
        __syncthreads();
        const uint32_t ab = smb + (c & 3) * STG_B;
        const uint32_t bb = ab + OPB_A;
        #pragma unroll
        for (int s = 0; s < 2; ++s) {
            uint32_t af[4][4], bq[2][4];
            #pragma unroll
            for (int mt = 0; mt < 4; ++mt) {
                if (TRA)
                    ldm4t(af[mt], ab + a_row_t + 32 * mt + s * (16 * APITCH_T));
                else
                    ldm4(af[mt], ab + a_row + mt * (16 * ROWB) + s * 32);
            }
            #pragma unroll
            for (int np = 0; np < 2; ++np)
                ldm4(bq[np], bb + b_row + np * (16 * ROWB) + s * 32);
            #pragma unroll
            for (int mt = 0; mt < 4; ++mt)
                #pragma unroll
                for (int nt = 0; nt < 4; ++nt)
                    mma_f16(acc[mt][nt],
                            af[mt][0], af[mt][1], af[mt][2], af[mt][3],
                            bq[nt >> 1][(nt & 1) * 2], bq[nt >> 1][(nt & 1) * 2 + 1]);
        }
        if (c + 3 < NC) issueChunk(c + 3, (c + 3) & 3);
        cpa_commit();
    }

    // ---- epilogue ----
    if (MODE == 1) {
        float csum0[4] = {0.f, 0.f, 0.f, 0.f};
        float csum1[4] = {0.f, 0.f, 0.f, 0.f};
        #pragma unroll
        for (int mt = 0; mt < 4; ++mt) {
            const int row0 = m0 + m_base + 16 * mt + g;
            const int rm0 = MR[z * 2048 + row0];
            const int rm1 = MR[z * 2048 + row0 + 8];
            float rsum0 = 0.f, rsum1 = 0.f;
            #pragma unroll
            for (int nt = 0; nt < 4; ++nt) {
                const int col0 = n0 + n_base + 8 * nt + 2 * tg;
                const int2 cm = *(const int2*)&MCm[z * 2048 + col0];
                float e00 = (rm0 * cm.x == 0) ? EXPM : __expf(acc[mt][nt][0] * SCALE);
                float e01 = (rm0 * cm.y == 0) ? EXPM : __expf(acc[mt][nt][1] * SCALE);
                float e10 = (rm1 * cm.x == 0) ? EXPM : __expf(acc[mt][nt][2] * SCALE);
                float e11 = (rm1 * cm.y == 0) ? EXPM : __expf(acc[mt][nt][3] * SCALE);
                __half2 p0 = __floats2half2_rn(e00, e01);
                __half2 p1 = __floats2half2_rn(e10, e11);
                *(__half2*)(Ch + (size_t)row0 * 2048 + col0)       = p0;
                *(__half2*)(Ch + (size_t)(row0 + 8) * 2048 + col0) = p1;
                float2 r0 = __half22float2(p0);
                float2 r1 = __half22float2(p1);
                rsum0 += r0.x + r0.y;
                rsum1 += r1.x + r1.y;
                csum0[nt] += r0.x + r1.x;
                csum1[nt] += r0.y + r1.y;
            }
            rsum0 += __shfl_xor_sync(0xffffffffu, rsum0, 1);
            rsum0 += __shfl_xor_sync(0xffffffffu, rsum0, 2);
            rsum1 += __shfl_xor_sync(0xffffffffu, rsum1, 1);
            rsum1 += __shfl_xor_sync(0xffffffffu, rsum1, 2);
            if (tg == 0) {
                atomicAdd(&g_rsum[z * 2048 + row0],     rsum0);
                atomicAdd(&g_rsum[z * 2048 + row0 + 8], rsum1);
            }
        }
        #pragma unroll
        for (int nt = 0; nt < 4; ++nt) {
            float c0 = csum0[nt], c1 = csum1[nt];
            #pragma unroll
            for (int o = 4; o <= 16; o <<= 1) {
                c0 += __shfl_xor_sync(0xffffffffu, c0, o);
                c1 += __shfl_xor_sync(0xffffffffu, c1, o);
            }
            if (g == 0) {
                const int col0 = n0 + n_base + 8 * nt + 2 * tg;
                atomicAdd(&g_csum[z * 2048 + col0],     c0);
                atomicAdd(&g_csum[z * 2048 + col0 + 1], c1);
            }
        }
    } else if (MODE == 0) {
        #pragma unroll
        for (int mt = 0; mt < 4; ++mt) {
            const int row0 = m0 + m_base + 16 * mt + g;
            #pragma unroll
            for (int nt = 0; nt < 4; ++nt) {
                const int col0 = n0 + n_base + 8 * nt + 2 * tg;
                const float2 bv = *(const float2*)(aux + col0);
                *(__half2*)(Ch + (size_t)row0 * 512 + col0) =
                    __floats2half2_rn(acc[mt][nt][0] + bv.x, acc[mt][nt][1] + bv.y);
                *(__half2*)(Ch + (size_t)(row0 + 8) * 512 + col0) =
                    __floats2half2_rn(acc[mt][nt][2] + bv.x, acc[mt][nt][3] + bv.y);
            }
        }
    } else {
        #pragma unroll
        for (int mt = 0; mt < 4; ++mt) {
            const int row0 = m0 + m_base + 16 * mt + g;
            #pragma unroll
            for (int nt = 0; nt < 4; ++nt) {
                const int col0 = n0 + n_base + 8 * nt + 2 * tg;
                const float2 e0 = *(const float2*)(aux + (size_t)row0 * 512 + col0);
                const float2 e1 = *(const float2*)(aux + (size_t)(row0 + 8) * 512 + col0);
                *(float2*)(Cf + (size_t)row0 * 512 + col0) =
                    make_float2(acc[mt][nt][0] + e0.x, acc[mt][nt][1] + e0.y);
                *(float2*)(Cf + (size_t)(row0 + 8) * 512 + col0) =
                    make_float2(acc[mt][nt][2] + e1.x, acc[mt][nt][3] + e1.y);
            }
        }
    }
}

// ---------------------------------------------------------------------------
// prep: fp32 src -> fp16 transpose (+ straight fp16 copy for inputs)
// DSTSEL: 0 wat (+zero sums), 1 wbt, 2 iat(+iha), 3 ibt(+ihb)
// ---------------------------------------------------------------------------
template <int DSTSEL>
__global__ void __launch_bounds__(256) prep_k(const float* __restrict__ src,
                                              int R, int C)
{
    __shared__ float tile[32][33];
    __half* tbase = (DSTSEL == 0) ? g_wat : (DSTSEL == 1) ? g_wbt
                  : (DSTSEL == 2) ? g_iat : g_ibt;
    __half* cbase = (DSTSEL == 2) ? g_iha : (DSTSEL == 3) ? g_ihb : nullptr;
    const int z = blockIdx.z;
    const float* s = src + (size_t)z * R * C;
    __half* d = tbase + (size_t)z * R * C;

    if (DSTSEL == 0) {           // fused zeroing of fused-sum accumulators
        const int lin = (blockIdx.y * gridDim.x + blockIdx.x) * 256
                      + threadIdx.y * 32 + threadIdx.x;
        if (lin < NB * 2048) { g_rsum[lin] = 0.f; g_csum[lin] = 0.f; }
    }

    int x = blockIdx.x * 32 + threadIdx.x;
    int y = blockIdx.y * 32 + threadIdx.y;
    #pragma unroll
    for (int j = 0; j < 32; j += 8) {
        float v = s[(size_t)(y + j) * C + x];
        tile[threadIdx.y + j][threadIdx.x] = v;
        if (DSTSEL >= 2)
            (cbase + (size_t)z * R * C)[(size_t)(y + j) * C + x] = __float2half(v);
    }
    __syncthreads();
    x = blockIdx.y * 32 + threadIdx.x;
    y = blockIdx.x * 32 + threadIdx.y;
    #pragma unroll
    for (int j = 0; j < 32; j += 8)
        d[(size_t)(y + j) * R + x] = __float2half(tile[threadIdx.x][threadIdx.y + j]);
}

// ---------------------------------------------------------------------------
__global__ void __launch_bounds__(256) recip_k()
{
    const int i = blockIdx.x * 256 + threadIdx.x;
    g_rinv[i] = 1.f / g_rsum[i];
    g_cinv[i] = 1.f / g_csum[i];
}
// scale g_ibt rows by cinv (y=0) / g_iat rows by rinv (y=1)
__global__ void __launch_bounds__(256) scaleb_k()
{
    const int idx = blockIdx.x * 256 + threadIdx.x;
    const int z = blockIdx.z;
    const int d = idx >> 8;
    const int j8 = (idx & 255) * 8;
    __half* base = (blockIdx.y ? g_iat : g_ibt) + (size_t)z * 512 * 2048 + (size_t)d * 2048 + j8;
    const float* inv = (blockIdx.y ? g_rinv : g_cinv) + z * 2048 + j8;
    uint4 v = *(uint4*)base;
    __half2* hp = (__half2*)&v;
    #pragma unroll
    for (int q = 0; q < 4; ++q) {
        float2 f = __half22float2(hp[q]);
        f.x *= inv[2 * q];
        f.y *= inv[2 * q + 1];
        hp[q] = __floats2half2_rn(f.x, f.y);
    }
    *(uint4*)base = v;
}

// ---------------------------------------------------------------------------
extern "C" void kernel_launch(void* const* d_in, const int* in_sizes, int n_in,
                              void* d_out, int out_size)
{
    (void)in_sizes; (void)n_in; (void)out_size;
    const float* input_a = (const float*)d_in[0];
    const float* input_b = (const float*)d_in[1];
    const int*   mask_a  = (const int*)d_in[2];
    const int*   mask_b  = (const int*)d_in[3];
    const float* ba      = (const float*)d_in[5];
    const float* Wa      = (const float*)d_in[4];
    const float* Wb      = (const float*)d_in[6];
    const float* bb      = (const float*)d_in[7];
    float* out = (float*)d_out;

    static bool attr_done = false;
    if (!attr_done) {
        cudaFuncSetAttribute(tc_gemm<0,0>, cudaFuncAttributeMaxDynamicSharedMemorySize, DYN_SMEM);
        cudaFuncSetAttribute(tc_gemm<0,1>, cudaFuncAttributeMaxDynamicSharedMemorySize, DYN_SMEM);
        cudaFuncSetAttribute(tc_gemm<1,0>, cudaFuncAttributeMaxDynamicSharedMemorySize, DYN_SMEM);
        cudaFuncSetAttribute(tc_gemm<2,0>, cudaFuncAttributeMaxDynamicSharedMemorySize, DYN_SMEM);
        cudaFuncSetAttribute(tc_gemm<3,0>, cudaFuncAttributeMaxDynamicSharedMemorySize, DYN_SMEM);
        attr_done = true;
    }

    // prep: fp16 transposes + fp16 input copies (+ sum zeroing in prep<0>)
    prep_k<0><<<dim3(16, 16, 1),  dim3(32, 8)>>>(Wa, 512, 512);
    prep_k<1><<<dim3(16, 16, 1),  dim3(32, 8)>>>(Wb, 512, 512);
    prep_k<2><<<dim3(16, 64, NB), dim3(32, 8)>>>(input_a, 2048, 512);
    prep_k<3><<<dim3(16, 64, NB), dim3(32, 8)>>>(input_b, 2048, 512);

    // projections -> fp16 mapped
    tc_gemm<0,0><<<dim3(4, 128, 1), 256, DYN_SMEM>>>(ba, nullptr, nullptr, nullptr);
    tc_gemm<0,1><<<dim3(4, 128, 1), 256, DYN_SMEM>>>(bb, nullptr, nullptr, nullptr);

    // masked exp-scores -> g_s (fp16) + fused row/col sums
    tc_gemm<1,0><<<dim3(16, 16, NB), 256, DYN_SMEM>>>(nullptr, mask_a, mask_b, nullptr);

    // denominators -> reciprocals, fold into B operands
    recip_k<<<NB * 2048 / 256, 256>>>();
    scaleb_k<<<dim3(512, 2, NB), 256>>>();

    // attention-weighted outputs + residual
    tc_gemm<2,0><<<dim3(4, 16, NB), 256, DYN_SMEM>>>(input_a, nullptr, nullptr, out);
    tc_gemm<3,0><<<dim3(4, 16, NB), 256, DYN_SMEM>>>(input_b, nullptr, nullptr,
                                                     out + (size_t)NB * NLA * ND);
}

// round 8
// speedup vs baseline: 7.4791x; 1.0364x over previous
#include <cuda_runtime.h>
#include <cuda_fp16.h>
#include <cstdint>

// ---------------------------------------------------------------------------
// CrossAttention, fp16 dataflow, cp.async + ldmatrix(+trans) mma.sync GEMMs.
// 6 launches: prep_w, prep_io, proj(a+b), scores(+fused sums), scaleb(+recip),
// out(a+b merged).
// ---------------------------------------------------------------------------

namespace {
constexpr int NB = 8, NLA = 2048, NLB = 2048, ND = 512, NH = 512;
constexpr float SCALE = 0.04419417382415922f;   // 1/sqrt(512)
constexpr float EXPM  = 1e-6f;                   // masked-entry E value

constexpr int BM = 128, BN = 128, BK = 32;       // chunk = 2 k16 steps
constexpr int ROWB = 80;                          // operand row pitch (bytes)
constexpr int OPB_STD = BM * ROWB;                // 10240
constexpr int APITCH_T = 272;                     // trans-A pitch (32 rows x 256B)
constexpr int STG_B = 2 * OPB_STD;                // 20480 per stage
constexpr int NSTG = 4;
constexpr int DYN_SMEM = NSTG * STG_B;            // 81920
}

// ---- scratch ----------------------------------------------------------------
__device__ __half g_wat[512 * 512];
__device__ __half g_wbt[512 * 512];
__device__ __half g_iha[NB * 2048 * 512];
__device__ __half g_ihb[NB * 2048 * 512];
__device__ __half g_iat[NB * 512 * 2048];         // input_a^T (later *rinv)
__device__ __half g_ibt[NB * 512 * 2048];         // input_b^T (later *cinv)
__device__ __half g_ma[NB * NLA * NH];
__device__ __half g_mb[NB * NLB * NH];
__device__ __half g_s [(size_t)NB * NLA * NLB];   // E[i][j]
__device__ float g_rsum[NB * NLA];
__device__ float g_csum[NB * NLB];

// ---- helpers ------------------------------------------------------------------
__device__ __forceinline__ uint32_t smem_u32(const void* p) {
    uint32_t a;
    asm("{ .reg .u64 t; cvta.to.shared.u64 t, %1; cvt.u32.u64 %0, t; }"
        : "=r"(a) : "l"(p));
    return a;
}
__device__ __forceinline__ void cpa16(uint32_t s, const void* g) {
    asm volatile("cp.async.cg.shared.global [%0], [%1], 16;" :: "r"(s), "l"(g));
}
__device__ __forceinline__ void cpa_commit() {
    asm volatile("cp.async.commit_group;" ::: "memory");
}
__device__ __forceinline__ void cpa_wait2() {
    asm volatile("cp.async.wait_group 2;" ::: "memory");
}
__device__ __forceinline__ void ldm4(uint32_t (&r)[4], uint32_t a) {
    asm volatile("ldmatrix.sync.aligned.m8n8.x4.shared.b16 {%0,%1,%2,%3}, [%4];"
                 : "=r"(r[0]), "=r"(r[1]), "=r"(r[2]), "=r"(r[3]) : "r"(a));
}
__device__ __forceinline__ void ldm4t(uint32_t (&r)[4], uint32_t a) {
    asm volatile("ldmatrix.sync.aligned.m8n8.x4.trans.shared.b16 {%0,%1,%2,%3}, [%4];"
                 : "=r"(r[0]), "=r"(r[1]), "=r"(r[2]), "=r"(r[3]) : "r"(a));
}
__device__ __forceinline__ void mma_f16(float (&d)[4],
                                        uint32_t a0, uint32_t a1, uint32_t a2, uint32_t a3,
                                        uint32_t b0, uint32_t b1) {
    asm volatile(
        "mma.sync.aligned.m16n8k16.row.col.f32.f16.f16.f32 "
        "{%0,%1,%2,%3}, {%4,%5,%6,%7}, {%8,%9}, {%0,%1,%2,%3};"
        : "+f"(d[0]), "+f"(d[1]), "+f"(d[2]), "+f"(d[3])
        : "r"(a0), "r"(a1), "r"(a2), "r"(a3), "r"(b0), "r"(b1));
}

// ---------------------------------------------------------------------------
// proj (merged a/b): C = input @ W^T + bias -> fp16 mapped. z selects set.
// ---------------------------------------------------------------------------
__global__ void __launch_bounds__(256, 2)
proj_k(const float* __restrict__ ba, const float* __restrict__ bb)
{
    constexpr int NC = 512 / BK;
    extern __shared__ __align__(16) char smem_raw[];
    const uint32_t smb = smem_u32(smem_raw);

    const int tid = threadIdx.x;
    const int sel = blockIdx.z;
    const int m0  = blockIdx.y * BM;
    const int n0  = blockIdx.x * BN;

    const __half* Ah = sel ? g_ihb : g_iha;
    const __half* Bh = sel ? g_wbt : g_wat;
    __half*       Ch = sel ? g_mb  : g_ma;
    const float* aux = sel ? bb : ba;

    const int prow = tid >> 1;
    const int pgrp = (tid & 1) * 2;
    const uint32_t soff = (uint32_t)(prow * ROWB + pgrp * 16);
    const __half* gA = Ah + (size_t)(m0 + prow) * 512 + pgrp * 8;
    const __half* gB = Bh + (size_t)(n0 + prow) * 512 + pgrp * 8;

    auto issueChunk = [&](int c, int st) {
        const uint32_t sbase = smb + st * STG_B;
        const __half* ga = gA + c * BK;
        const __half* gb = gB + c * BK;
        cpa16(sbase + soff, ga);
        cpa16(sbase + soff + 16, ga + 8);
        cpa16(sbase + OPB_STD + soff, gb);
        cpa16(sbase + OPB_STD + soff + 16, gb + 8);
    };

    const int warp = tid >> 5, lane = tid & 31;
    const int wm = warp >> 2, wn = warp & 3;
    const int m_base = wm * 64, n_base = wn * 32;
    const int g = lane >> 2, tg = lane & 3;

    const uint32_t a_row = (uint32_t)(m_base + (lane & 15)) * ROWB + (lane >> 4) * 16;
    const uint32_t b_row = (uint32_t)(n_base + ((lane >> 4) << 3) + (lane & 7)) * ROWB
                         + ((lane >> 3) & 1) * 16;

    float acc[4][4][4] = {};

    #pragma unroll
    for (int c = 0; c < 3; ++c) { issueChunk(c, c); cpa_commit(); }

    for (int c = 0; c < NC; ++c) {
        cpa_wait2();
        __syncthreads();
        const uint32_t ab = smb + (c & 3) * STG_B;
        const uint32_t bb2 = ab + OPB_STD;
        #pragma unroll
        for (int s = 0; s < 2; ++s) {
            uint32_t af[4][4], bq[2][4];
            #pragma unroll
            for (int mt = 0; mt < 4; ++mt)
                ldm4(af[mt], ab + a_row + mt * (16 * ROWB) + s * 32);
            #pragma unroll
            for (int np = 0; np < 2; ++np)
                ldm4(bq[np], bb2 + b_row + np * (16 * ROWB) + s * 32);
            #pragma unroll
            for (int mt = 0; mt < 4; ++mt)
                #pragma unroll
                for (int nt = 0; nt < 4; ++nt)
                    mma_f16(acc[mt][nt],
                            af[mt][0], af[mt][1], af[mt][2], af[mt][3],
                            bq[nt >> 1][(nt & 1) * 2], bq[nt >> 1][(nt & 1) * 2 + 1]);
        }
        if (c + 3 < NC) issueChunk(c + 3, (c + 3) & 3);
        cpa_commit();
    }

    #pragma unroll
    for (int mt = 0; mt < 4; ++mt) {
        const int row0 = m0 + m_base + 16 * mt + g;
        #pragma unroll
        for (int nt = 0; nt < 4; ++nt) {
            const int col0 = n0 + n_base + 8 * nt + 2 * tg;
            const float2 bv = *(const float2*)(aux + col0);
            *(__half2*)(Ch + (size_t)row0 * 512 + col0) =
                __floats2half2_rn(acc[mt][nt][0] + bv.x, acc[mt][nt][1] + bv.y);
            *(__half2*)(Ch + (size_t)(row0 + 8) * 512 + col0) =
                __floats2half2_rn(acc[mt][nt][2] + bv.x, acc[mt][nt][3] + bv.y);
        }
    }
}

// ---------------------------------------------------------------------------
// scores: E = exp(scale * ma.mb^T), masked -> EXPM; writes g_s + fused sums.
// ---------------------------------------------------------------------------
__global__ void __launch_bounds__(256, 2)
scores_k(const int* __restrict__ MR, const int* __restrict__ MCm)
{
    constexpr int NC = 512 / BK;
    extern __shared__ __align__(16) char smem_raw[];
    const uint32_t smb = smem_u32(smem_raw);

    const int tid = threadIdx.x;
    const int z   = blockIdx.z;
    const int m0  = blockIdx.y * BM;
    const int n0  = blockIdx.x * BN;

    const __half* Ah = g_ma + (size_t)z * 2048 * 512;
    const __half* Bh = g_mb + (size_t)z * 2048 * 512;
    __half*       Ch = g_s  + (size_t)z * NLA * NLB;

    const int prow = tid >> 1;
    const int pgrp = (tid & 1) * 2;
    const uint32_t soff = (uint32_t)(prow * ROWB + pgrp * 16);
    const __half* gA = Ah + (size_t)(m0 + prow) * 512 + pgrp * 8;
    const __half* gB = Bh + (size_t)(n0 + prow) * 512 + pgrp * 8;

    auto issueChunk = [&](int c, int st) {
        const uint32_t sbase = smb + st * STG_B;
        const __half* ga = gA + c * BK;
        const __half* gb = gB + c * BK;
        cpa16(sbase + soff, ga);
        cpa16(sbase + soff + 16, ga + 8);
        cpa16(sbase + OPB_STD + soff, gb);
        cpa16(sbase + OPB_STD + soff + 16, gb + 8);
    };

    const int warp = tid >> 5, lane = tid & 31;
    const int wm = warp >> 2, wn = warp & 3;
    const int m_base = wm * 64, n_base = wn * 32;
    const int g = lane >> 2, tg = lane & 3;

    const uint32_t a_row = (uint32_t)(m_base + (lane & 15)) * ROWB + (lane >> 4) * 16;
    const uint32_t b_row = (uint32_t)(n_base + ((lane >> 4) << 3) + (lane & 7)) * ROWB
                         + ((lane >> 3) & 1) * 16;

    float acc[4][4][4] = {};

    #pragma unroll
    for (int c = 0; c < 3; ++c) { issueChunk(c, c); cpa_commit(); }

    for (int c = 0; c < NC; ++c) {
        cpa_wait2();
        __syncthreads();
        const uint32_t ab = smb + (c & 3) * STG_B;
        const uint32_t bb2 = ab + OPB_STD;
        #pragma unroll
        for (int s = 0; s < 2; ++s) {
            uint32_t af[4][4], bq[2][4];
            #pragma unroll
            for (int mt = 0; mt < 4; ++mt)
                ldm4(af[mt], ab + a_row + mt * (16 * ROWB) + s * 32);
            #pragma unroll
            for (int np = 0; np < 2; ++np)
                ldm4(bq[np], bb2 + b_row + np * (16 * ROWB) + s * 32);
            #pragma unroll
            for (int mt = 0; mt < 4; ++mt)
                #pragma unroll
                for (int nt = 0; nt < 4; ++nt)
                    mma_f16(acc[mt][nt],
                            af[mt][0], af[mt][1], af[mt][2], af[mt][3],
                            bq[nt >> 1][(nt & 1) * 2], bq[nt >> 1][(nt & 1) * 2 + 1]);
        }
        if (c + 3 < NC) issueChunk(c + 3, (c + 3) & 3);
        cpa_commit();
    }

    float csum0[4] = {0.f, 0.f, 0.f, 0.f};
    float csum1[4] = {0.f, 0.f, 0.f, 0.f};
    #pragma unroll
    for (int mt = 0; mt < 4; ++mt) {
        const int row0 = m0 + m_base + 16 * mt + g;
        const int rm0 = MR[z * 2048 + row0];
        const int rm1 = MR[z * 2048 + row0 + 8];
        float rsum0 = 0.f, rsum1 = 0.f;
        #pragma unroll
        for (int nt = 0; nt < 4; ++nt) {
            const int col0 = n0 + n_base + 8 * nt + 2 * tg;
            const int2 cm = *(const int2*)&MCm[z * 2048 + col0];
            float e00 = (rm0 * cm.x == 0) ? EXPM : __expf(acc[mt][nt][0] * SCALE);
            float e01 = (rm0 * cm.y == 0) ? EXPM : __expf(acc[mt][nt][1] * SCALE);
            float e10 = (rm1 * cm.x == 0) ? EXPM : __expf(acc[mt][nt][2] * SCALE);
            float e11 = (rm1 * cm.y == 0) ? EXPM : __expf(acc[mt][nt][3] * SCALE);
            __half2 p0 = __floats2half2_rn(e00, e01);
            __half2 p1 = __floats2half2_rn(e10, e11);
            *(__half2*)(Ch + (size_t)row0 * 2048 + col0)       = p0;
            *(__half2*)(Ch + (size_t)(row0 + 8) * 2048 + col0) = p1;
            float2 r0 = __half22float2(p0);
            float2 r1 = __half22float2(p1);
            rsum0 += r0.x + r0.y;
            rsum1 += r1.x + r1.y;
            csum0[nt] += r0.x + r1.x;
            csum1[nt] += r0.y + r1.y;
        }
        rsum0 += __shfl_xor_sync(0xffffffffu, rsum0, 1);
        rsum0 += __shfl_xor_sync(0xffffffffu, rsum0, 2);
        rsum1 += __shfl_xor_sync(0xffffffffu, rsum1, 1);
        rsum1 += __shfl_xor_sync(0xffffffffu, rsum1, 2);
        if (tg == 0) {
            atomicAdd(&g_rsum[z * 2048 + row0],     rsum0);
            atomicAdd(&g_rsum[z * 2048 + row0 + 8], rsum1);
        }
    }
    #pragma unroll
    for (int nt = 0; nt < 4; ++nt) {
        float c0 = csum0[nt], c1 = csum1[nt];
        #pragma unroll
        for (int o = 4; o <= 16; o <<= 1) {
            c0 += __shfl_xor_sync(0xffffffffu, c0, o);
            c1 += __shfl_xor_sync(0xffffffffu, c1, o);
        }
        if (g == 0) {
            const int col0 = n0 + n_base + 8 * nt + 2 * tg;
            atomicAdd(&g_csum[z * 2048 + col0],     c0);
            atomicAdd(&g_csum[z * 2048 + col0 + 1], c1);
        }
    }
}

// ---------------------------------------------------------------------------
// out (merged): z<8 -> out_a = E @ ibt + resid_a ; z>=8 -> out_b = E^T @ iat + resid_b.
// ---------------------------------------------------------------------------
__global__ void __launch_bounds__(256, 2)
out_k(const float* __restrict__ ia, const float* __restrict__ ib,
      float* __restrict__ OUT)
{
    constexpr int NC = 2048 / BK;
    extern __shared__ __align__(16) char smem_raw[];
    const uint32_t smb = smem_u32(smem_raw);

    const int tid = threadIdx.x;
    const bool tra = blockIdx.z >= 8;
    const int z   = blockIdx.z & 7;
    const int m0  = blockIdx.y * BM;
    const int n0  = blockIdx.x * BN;

    const __half* Ah = g_s + (size_t)z * NLA * NLB;
    const __half* Bh = (tra ? g_iat : g_ibt) + (size_t)z * ND * 2048;
    const float* aux = (tra ? ib : ia) + (size_t)z * 2048 * ND;
    float* Cf = OUT + (tra ? (size_t)NB * NLA * ND : 0) + (size_t)z * 2048 * ND;

    // producer geometry
    const int prow = tid >> 1;
    const int pgrp = (tid & 1) * 2;
    const uint32_t soffB = (uint32_t)(prow * ROWB + pgrp * 16);
    const __half* gB = Bh + (size_t)(n0 + prow) * 2048 + pgrp * 8;
    const int tarow = tid >> 3;
    const int tacol = (tid & 7) * 16;
    const uint32_t soffAT = (uint32_t)(tarow * APITCH_T + tacol * 2);
    const __half* gA_std = Ah + (size_t)(m0 + prow) * 2048 + pgrp * 8;
    const __half* gA_tra = Ah + m0 + tacol;

    auto issueChunk = [&](int c, int st) {
        const uint32_t sbase = smb + st * STG_B;
        if (tra) {
            const __half* ga = gA_tra + (size_t)(c * BK + tarow) * 2048;
            cpa16(sbase + soffAT, ga);
            cpa16(sbase + soffAT + 16, ga + 8);
        } else {
            const uint32_t sa = sbase + (uint32_t)(prow * ROWB + pgrp * 16);
            const __half* ga = gA_std + c * BK;
            cpa16(sa, ga);
            cpa16(sa + 16, ga + 8);
        }
        const uint32_t sb = sbase + OPB_STD + soffB;
        const __half* gb = gB + c * BK;
        cpa16(sb, gb);
        cpa16(sb + 16, gb + 8);
    };

    const int warp = tid >> 5, lane = tid & 31;
    const int wm = warp >> 2, wn = warp & 3;
    const int m_base = wm * 64, n_base = wn * 32;
    const int g = lane >> 2, tg = lane & 3;

    const uint32_t a_row = (uint32_t)(m_base + (lane & 15)) * ROWB + (lane >> 4) * 16;
    const uint32_t a_row_t = (uint32_t)((lane >> 4) * 8 + (lane & 7)) * APITCH_T
                           + ((lane >> 3) & 1) * 16 + (uint32_t)m_base * 2;
    const uint32_t b_row = (uint32_t)(n_base + ((lane >> 4) << 3) + (lane & 7)) * ROWB
                         + ((lane >> 3) & 1) * 16;

    float acc[4][4][4] = {};

    #pragma unroll
    for (int c = 0; c < 3; ++c) { issueChunk(c, c); cpa_commit(); }

    for (int c = 0; c < NC; ++c) {
        cpa_wait2();
        __syncthreads();
        const uint32_t ab = smb + (c & 3) * STG_B;
        const uint32_t bb2 = ab + OPB_STD;
        #pragma unroll
        for (int s = 0; s < 2; ++s) {
            uint32_t af[4][4], bq[2][4];
            if (tra) {
                #pragma unroll
                for (int mt = 0; mt < 4; ++mt)
                    ldm4t(af[mt], ab + a_row_t + 32 * mt + s * (16 * APITCH_T));
            } else {
                #pragma unroll
                for (int mt = 0; mt < 4; ++mt)
                    ldm4(af[mt], ab + a_row + mt * (16 * ROWB) + s * 32);
            }
            #pragma unroll
            for (int np = 0; np < 2; ++np)
                ldm4(bq[np], bb2 + b_row + np * (16 * ROWB) + s * 32);
            #pragma unroll
            for (int mt = 0; mt < 4; ++mt)
                #pragma unroll
                for (int nt = 0; nt < 4; ++nt)
                    mma_f16(acc[mt][nt],
                            af[mt][0], af[mt][1], af[mt][2], af[mt][3],
                            bq[nt >> 1][(nt & 1) * 2], bq[nt >> 1][(nt & 1) * 2 + 1]);
        }
        if (c + 3 < NC) issueChunk(c + 3, (c + 3) & 3);
        cpa_commit();
    }

    #pragma unroll
    for (int mt = 0; mt < 4; ++mt) {
        const int row0 = m0 + m_base + 16 * mt + g;
        #pragma unroll
        for (int nt = 0; nt < 4; ++nt) {
            const int col0 = n0 + n_base + 8 * nt + 2 * tg;
            const float2 e0 = *(const float2*)(aux + (size_t)row0 * 512 + col0);
            const float2 e1 = *(const float2*)(aux + (size_t)(row0 + 8) * 512 + col0);
            *(float2*)(Cf + (size_t)row0 * 512 + col0) =
                make_float2(acc[mt][nt][0] + e0.x, acc[mt][nt][1] + e0.y);
            *(float2*)(Cf + (size_t)(row0 + 8) * 512 + col0) =
                make_float2(acc[mt][nt][2] + e1.x, acc[mt][nt][3] + e1.y);
        }
    }
}

// ---------------------------------------------------------------------------
// prep_w: W (fp32) -> W^T fp16 (z: 0=Wa, 1=Wb); z==0 also zeroes sums.
// ---------------------------------------------------------------------------
__global__ void __launch_bounds__(256)
prep_w(const float* __restrict__ Wa, const float* __restrict__ Wb)
{
    __shared__ float tile[32][33];
    const int sel = blockIdx.z;
    const float* s = sel ? Wb : Wa;
    __half* d = sel ? g_wbt : g_wat;

    if (sel == 0) {
        const int lin = (blockIdx.y * gridDim.x + blockIdx.x) * 256
                      + threadIdx.y * 32 + threadIdx.x;
        if (lin < NB * 2048) { g_rsum[lin] = 0.f; g_csum[lin] = 0.f; }
    }

    int x = blockIdx.x * 32 + threadIdx.x;
    int y = blockIdx.y * 32 + threadIdx.y;
    #pragma unroll
    for (int j = 0; j < 32; j += 8)
        tile[threadIdx.y + j][threadIdx.x] = s[(size_t)(y + j) * 512 + x];
    __syncthreads();
    x = blockIdx.y * 32 + threadIdx.x;
    y = blockIdx.x * 32 + threadIdx.y;
    #pragma unroll
    for (int j = 0; j < 32; j += 8)
        d[(size_t)(y + j) * 512 + x] = __float2half(tile[threadIdx.x][threadIdx.y + j]);
}

// ---------------------------------------------------------------------------
// prep_io (merged a/b): fp32 input -> fp16 copy + fp16 transpose. z>=8 -> b.
// ---------------------------------------------------------------------------
__global__ void __launch_bounds__(256)
prep_io(const float* __restrict__ ia, const float* __restrict__ ib)
{
    __shared__ float tile[32][33];
    const bool sel = blockIdx.z >= 8;
    const int z = blockIdx.z & 7;
    const float* s = (sel ? ib : ia) + (size_t)z * 2048 * 512;
    __half* d = (sel ? g_ibt : g_iat) + (size_t)z * 2048 * 512;
    __half* c = (sel ? g_ihb : g_iha) + (size_t)z * 2048 * 512;

    int x = blockIdx.x * 32 + threadIdx.x;
    int y = blockIdx.y * 32 + threadIdx.y;
    #pragma unroll
    for (int j = 0; j < 32; j += 8) {
        float v = s[(size_t)(y + j) * 512 + x];
        tile[threadIdx.y + j][threadIdx.x] = v;
        c[(size_t)(y + j) * 512 + x] = __float2half(v);
    }
    __syncthreads();
    x = blockIdx.y * 32 + threadIdx.x;
    y = blockIdx.x * 32 + threadIdx.y;
    #pragma unroll
    for (int j = 0; j < 32; j += 8)
        d[(size_t)(y + j) * 2048 + x] = __float2half(tile[threadIdx.x][threadIdx.y + j]);
}

// ---------------------------------------------------------------------------
// scaleb (+fused recip): g_ibt *= 1/csum (y=0), g_iat *= 1/rsum (y=1).
// ---------------------------------------------------------------------------
__global__ void __launch_bounds__(256)
scaleb_k()
{
    const int idx = blockIdx.x * 256 + threadIdx.x;
    const int z = blockIdx.z;
    const int d = idx >> 8;
    const int j8 = (idx & 255) * 8;
    __half* base = (blockIdx.y ? g_iat : g_ibt) + (size_t)z * 512 * 2048 + (size_t)d * 2048 + j8;
    const float* sum = (blockIdx.y ? g_rsum : g_csum) + z * 2048 + j8;
    float inv[8];
    #pragma unroll
    for (int q = 0; q < 8; ++q) inv[q] = __frcp_rn(sum[q]);
    uint4 v = *(uint4*)base;
    __half2* hp = (__half2*)&v;
    #pragma unroll
    for (int q = 0; q < 4; ++q) {
        float2 f = __half22float2(hp[q]);
        f.x *= inv[2 * q];
        f.y *= inv[2 * q + 1];
        hp[q] = __floats2half2_rn(f.x, f.y);
    }
    *(uint4*)base = v;
}

// ---------------------------------------------------------------------------
extern "C" void kernel_launch(void* const* d_in, const int* in_sizes, int n_in,
                              void* d_out, int out_size)
{
    (void)in_sizes; (void)n_in; (void)out_size;
    const float* input_a = (const float*)d_in[0];
    const float* input_b = (const float*)d_in[1];
    const int*   mask_a  = (const int*)d_in[2];
    const int*   mask_b  = (const int*)d_in[3];
    const float* Wa      = (const float*)d_in[4];
    const float* ba      = (const float*)d_in[5];
    const float* Wb      = (const float*)d_in[6];
    const float* bb      = (const float*)d_in[7];
    float* out = (float*)d_out;

    static bool attr_done = false;
    if (!attr_done) {
        cudaFuncSetAttribute(proj_k,   cudaFuncAttributeMaxDynamicSharedMemorySize, DYN_SMEM);
        cudaFuncSetAttribute(scores_k, cudaFuncAttributeMaxDynamicSharedMemorySize, DYN_SMEM);
        cudaFuncSetAttribute(out_k,    cudaFuncAttributeMaxDynamicSharedMemorySize, DYN_SMEM);
        attr_done = true;
    }

    // prep: weight transposes (+sum zeroing), input copies+transposes
    prep_w <<<dim3(16, 16, 2),  dim3(32, 8)>>>(Wa, Wb);
    prep_io<<<dim3(16, 64, 16), dim3(32, 8)>>>(input_a, input_b);

    // projections (a+b merged) -> fp16 mapped
    proj_k<<<dim3(4, 128, 2), 256, DYN_SMEM>>>(ba, bb);

    // masked exp-scores -> g_s (fp16) + fused row/col sums
    scores_k<<<dim3(16, 16, NB), 256, DYN_SMEM>>>(mask_a, mask_b);

    // fold 1/sums into B operands
    scaleb_k<<<dim3(512, 2, NB), 256>>>();

    // attention-weighted outputs + residual (a+b merged)
    out_k<<<dim3(4, 16, 16), 256, DYN_SMEM>>>(input_a, input_b, out);
}

// round 9
// speedup vs baseline: 7.9628x; 1.0647x over previous
#include <cuda_runtime.h>
#include <cuda_fp16.h>
#include <cstdint>

// ---------------------------------------------------------------------------
// CrossAttention, fp16 dataflow, cp.async + ldmatrix(+trans) mma.sync GEMMs.
// 64x64 warp tiles (4 warps / 128 threads per CTA), 128x128 CTA tiles.
// ---------------------------------------------------------------------------

namespace {
constexpr int NB = 8, NLA = 2048, NLB = 2048, ND = 512, NH = 512;
constexpr float SCALE = 0.04419417382415922f;   // 1/sqrt(512)
constexpr float EXPM  = 1e-6f;                   // masked-entry E value

constexpr int BM = 128, BN = 128, BK = 32;       // chunk = 2 k16 steps
constexpr int ROWB = 80;                          // operand row pitch (bytes)
constexpr int OPB_STD = BM * ROWB;                // 10240
constexpr int APITCH_T = 272;                     // trans-A pitch (32 rows x 256B)
constexpr int STG_B = 2 * OPB_STD;                // 20480 per stage
constexpr int NSTG = 4;
constexpr int DYN_SMEM = NSTG * STG_B;            // 81920
}

// ---- scratch ----------------------------------------------------------------
__device__ __half g_wat[512 * 512];
__device__ __half g_wbt[512 * 512];
__device__ __half g_iha[NB * 2048 * 512];
__device__ __half g_ihb[NB * 2048 * 512];
__device__ __half g_iat[NB * 512 * 2048];         // input_a^T (later *rinv)
__device__ __half g_ibt[NB * 512 * 2048];         // input_b^T (later *cinv)
__device__ __half g_ma[NB * NLA * NH];
__device__ __half g_mb[NB * NLB * NH];
__device__ __half g_s [(size_t)NB * NLA * NLB];   // E[i][j]
__device__ float g_rsum[NB * NLA];
__device__ float g_csum[NB * NLB];

// ---- helpers ------------------------------------------------------------------
__device__ __forceinline__ uint32_t smem_u32(const void* p) {
    uint32_t a;
    asm("{ .reg .u64 t; cvta.to.shared.u64 t, %1; cvt.u32.u64 %0, t; }"
        : "=r"(a) : "l"(p));
    return a;
}
__device__ __forceinline__ void cpa16(uint32_t s, const void* g) {
    asm volatile("cp.async.cg.shared.global [%0], [%1], 16;" :: "r"(s), "l"(g));
}
__device__ __forceinline__ void cpa_commit() {
    asm volatile("cp.async.commit_group;" ::: "memory");
}
__device__ __forceinline__ void cpa_wait2() {
    asm volatile("cp.async.wait_group 2;" ::: "memory");
}
__device__ __forceinline__ void ldm4(uint32_t (&r)[4], uint32_t a) {
    asm volatile("ldmatrix.sync.aligned.m8n8.x4.shared.b16 {%0,%1,%2,%3}, [%4];"
                 : "=r"(r[0]), "=r"(r[1]), "=r"(r[2]), "=r"(r[3]) : "r"(a));
}
__device__ __forceinline__ void ldm4t(uint32_t (&r)[4], uint32_t a) {
    asm volatile("ldmatrix.sync.aligned.m8n8.x4.trans.shared.b16 {%0,%1,%2,%3}, [%4];"
                 : "=r"(r[0]), "=r"(r[1]), "=r"(r[2]), "=r"(r[3]) : "r"(a));
}
__device__ __forceinline__ void mma_f16(float (&d)[4],
                                        uint32_t a0, uint32_t a1, uint32_t a2, uint32_t a3,
                                        uint32_t b0, uint32_t b1) {
    asm volatile(
        "mma.sync.aligned.m16n8k16.row.col.f32.f16.f16.f32 "
        "{%0,%1,%2,%3}, {%4,%5,%6,%7}, {%8,%9}, {%0,%1,%2,%3};"
        : "+f"(d[0]), "+f"(d[1]), "+f"(d[2]), "+f"(d[3])
        : "r"(a0), "r"(a1), "r"(a2), "r"(a3), "r"(b0), "r"(b1));
}

// ---------------------------------------------------------------------------
// proj (merged a/b): C = input @ W^T + bias -> fp16 mapped. z selects set.
// ---------------------------------------------------------------------------
__global__ void __launch_bounds__(128, 2)
proj_k(const float* __restrict__ ba, const float* __restrict__ bb)
{
    constexpr int NC = 512 / BK;
    extern __shared__ __align__(16) char smem_raw[];
    const uint32_t smb = smem_u32(smem_raw);

    const int tid = threadIdx.x;
    const int sel = blockIdx.z;
    const int m0  = blockIdx.y * BM;
    const int n0  = blockIdx.x * BN;

    const __half* Ah = sel ? g_ihb : g_iha;
    const __half* Bh = sel ? g_wbt : g_wat;
    __half*       Ch = sel ? g_mb  : g_ma;
    const float* aux = sel ? bb : ba;

    const int r4 = tid >> 2;
    const int q4 = tid & 3;
    const uint32_t soff = (uint32_t)(r4 * ROWB + q4 * 16);
    const __half* gA = Ah + (size_t)(m0 + r4) * 512 + q4 * 8;
    const __half* gB = Bh + (size_t)(n0 + r4) * 512 + q4 * 8;

    auto issueChunk = [&](int c, int st) {
        const uint32_t sbase = smb + st * STG_B;
        #pragma unroll
        for (int p = 0; p < 4; ++p) {
            cpa16(sbase + soff + p * (32 * ROWB), gA + c * BK + (size_t)p * (32 * 512));
            cpa16(sbase + OPB_STD + soff + p * (32 * ROWB),
                  gB + c * BK + (size_t)p * (32 * 512));
        }
    };

    const int warp = tid >> 5, lane = tid & 31;
    const int wm = warp >> 1, wn = warp & 1;
    const int m_base = wm * 64, n_base = wn * 64;
    const int g = lane >> 2, tg = lane & 3;

    const uint32_t a_row = (uint32_t)(m_base + (lane & 15)) * ROWB + (lane >> 4) * 16;
    const uint32_t b_row = (uint32_t)(n_base + ((lane >> 4) << 3) + (lane & 7)) * ROWB
                         + ((lane >> 3) & 1) * 16;

    float acc[4][8][4] = {};

    #pragma unroll
    for (int c = 0; c < 3; ++c) { issueChunk(c, c); cpa_commit(); }

    for (int c = 0; c < NC; ++c) {
        cpa_wait2();
        __syncthreads();
        const uint32_t ab = smb + (c & 3) * STG_B;
        const uint32_t bb2 = ab + OPB_STD;
        #pragma unroll
        for (int s = 0; s < 2; ++s) {
            uint32_t af[4][4], bq[4][4];
            #pragma unroll
            for (int mt = 0; mt < 4; ++mt)
                ldm4(af[mt], ab + a_row + mt * (16 * ROWB) + s * 32);
            #pragma unroll
            for (int np = 0; np < 4; ++np)
                ldm4(bq[np], bb2 + b_row + np * (16 * ROWB) + s * 32);
            #pragma unroll
            for (int mt = 0; mt < 4; ++mt)
                #pragma unroll
                for (int nt = 0; nt < 8; ++nt)
                    mma_f16(acc[mt][nt],
                            af[mt][0], af[mt][1], af[mt][2], af[mt][3],
                            bq[nt >> 1][(nt & 1) * 2], bq[nt >> 1][(nt & 1) * 2 + 1]);
        }
        if (c + 3 < NC) issueChunk(c + 3, (c + 3) & 3);
        cpa_commit();
    }

    #pragma unroll
    for (int mt = 0; mt < 4; ++mt) {
        const int row0 = m0 + m_base + 16 * mt + g;
        #pragma unroll
        for (int nt = 0; nt < 8; ++nt) {
            const int col0 = n0 + n_base + 8 * nt + 2 * tg;
            const float2 bv = *(const float2*)(aux + col0);
            *(__half2*)(Ch + (size_t)row0 * 512 + col0) =
                __floats2half2_rn(acc[mt][nt][0] + bv.x, acc[mt][nt][1] + bv.y);
            *(__half2*)(Ch + (size_t)(row0 + 8) * 512 + col0) =
                __floats2half2_rn(acc[mt][nt][2] + bv.x, acc[mt][nt][3] + bv.y);
        }
    }
}

// ---------------------------------------------------------------------------
// scores: E = exp(scale * ma.mb^T), masked -> EXPM; writes g_s + fused sums.
// ---------------------------------------------------------------------------
__global__ void __launch_bounds__(128, 2)
scores_k(const int* __restrict__ MR, const int* __restrict__ MCm)
{
    constexpr int NC = 512 / BK;
    extern __shared__ __align__(16) char smem_raw[];
    const uint32_t smb = smem_u32(smem_raw);

    const int tid = threadIdx.x;
    const int z   = blockIdx.z;
    const int m0  = blockIdx.y * BM;
    const int n0  = blockIdx.x * BN;

    const __half* Ah = g_ma + (size_t)z * 2048 * 512;
    const __half* Bh = g_mb + (size_t)z * 2048 * 512;
    __half*       Ch = g_s  + (size_t)z * NLA * NLB;

    const int r4 = tid >> 2;
    const int q4 = tid & 3;
    const uint32_t soff = (uint32_t)(r4 * ROWB + q4 * 16);
    const __half* gA = Ah + (size_t)(m0 + r4) * 512 + q4 * 8;
    const __half* gB = Bh + (size_t)(n0 + r4) * 512 + q4 * 8;

    auto issueChunk = [&](int c, int st) {
        const uint32_t sbase = smb + st * STG_B;
        #pragma unroll
        for (int p = 0; p < 4; ++p) {
            cpa16(sbase + soff + p * (32 * ROWB), gA + c * BK + (size_t)p * (32 * 512));
            cpa16(sbase + OPB_STD + soff + p * (32 * ROWB),
                  gB + c * BK + (size_t)p * (32 * 512));
        }
    };

    const int warp = tid >> 5, lane = tid & 31;
    const int wm = warp >> 1, wn = warp & 1;
    const int m_base = wm * 64, n_base = wn * 64;
    const int g = lane >> 2, tg = lane & 3;

    const uint32_t a_row = (uint32_t)(m_base + (lane & 15)) * ROWB + (lane >> 4) * 16;
    const uint32_t b_row = (uint32_t)(n_base + ((lane >> 4) << 3) + (lane & 7)) * ROWB
                         + ((lane >> 3) & 1) * 16;

    float acc[4][8][4] = {};

    #pragma unroll
    for (int c = 0; c < 3; ++c) { issueChunk(c, c); cpa_commit(); }

    for (int c = 0; c < NC; ++c) {
        cpa_wait2();
        __syncthreads();
        const uint32_t ab = smb + (c & 3) * STG_B;
        const uint32_t bb2 = ab + OPB_STD;
        #pragma unroll
        for (int s = 0; s < 2; ++s) {
            uint32_t af[4][4], bq[4][4];
            #pragma unroll
            for (int mt = 0; mt < 4; ++mt)
                ldm4(af[mt], ab + a_row + mt * (16 * ROWB) + s * 32);
            #pragma unroll
            for (int np = 0; np < 4; ++np)
                ldm4(bq[np], bb2 + b_row + np * (16 * ROWB) + s * 32);
            #pragma unroll
            for (int mt = 0; mt < 4; ++mt)
                #pragma unroll
                for (int nt = 0; nt < 8; ++nt)
                    mma_f16(acc[mt][nt],
                            af[mt][0], af[mt][1], af[mt][2], af[mt][3],
                            bq[nt >> 1][(nt & 1) * 2], bq[nt >> 1][(nt & 1) * 2 + 1]);
        }
        if (c + 3 < NC) issueChunk(c + 3, (c + 3) & 3);
        cpa_commit();
    }

    float csum0[8], csum1[8];
    #pragma unroll
    for (int nt = 0; nt < 8; ++nt) { csum0[nt] = 0.f; csum1[nt] = 0.f; }
    #pragma unroll
    for (int mt = 0; mt < 4; ++mt) {
        const int row0 = m0 + m_base + 16 * mt + g;
        const int rm0 = MR[z * 2048 + row0];
        const int rm1 = MR[z * 2048 + row0 + 8];
        float rsum0 = 0.f, rsum1 = 0.f;
        #pragma unroll
        for (int nt = 0; nt < 8; ++nt) {
            const int col0 = n0 + n_base + 8 * nt + 2 * tg;
            const int2 cm = *(const int2*)&MCm[z * 2048 + col0];
            float e00 = (rm0 * cm.x == 0) ? EXPM : __expf(acc[mt][nt][0] * SCALE);
            float e01 = (rm0 * cm.y == 0) ? EXPM : __expf(acc[mt][nt][1] * SCALE);
            float e10 = (rm1 * cm.x == 0) ? EXPM : __expf(acc[mt][nt][2] * SCALE);
            float e11 = (rm1 * cm.y == 0) ? EXPM : __expf(acc[mt][nt][3] * SCALE);
            __half2 p0 = __floats2half2_rn(e00, e01);
            __half2 p1 = __floats2half2_rn(e10, e11);
            *(__half2*)(Ch + (size_t)row0 * 2048 + col0)       = p0;
            *(__half2*)(Ch + (size_t)(row0 + 8) * 2048 + col0) = p1;
            float2 r0 = __half22float2(p0);
            float2 r1 = __half22float2(p1);
            rsum0 += r0.x + r0.y;
            rsum1 += r1.x + r1.y;
            csum0[nt] += r0.x + r1.x;
            csum1[nt] += r0.y + r1.y;
        }
        rsum0 += __shfl_xor_sync(0xffffffffu, rsum0, 1);
        rsum0 += __shfl_xor_sync(0xffffffffu, rsum0, 2);
        rsum1 += __shfl_xor_sync(0xffffffffu, rsum1, 1);
        rsum1 += __shfl_xor_sync(0xffffffffu, rsum1, 2);
        if (tg == 0) {
            atomicAdd(&g_rsum[z * 2048 + row0],     rsum0);
            atomicAdd(&g_rsum[z * 2048 + row0 + 8], rsum1);
        }
    }
    #pragma unroll
    for (int nt = 0; nt < 8; ++nt) {
        float c0 = csum0[nt], c1 = csum1[nt];
        #pragma unroll
        for (int o = 4; o <= 16; o <<= 1) {
            c0 += __shfl_xor_sync(0xffffffffu, c0, o);
            c1 += __shfl_xor_sync(0xffffffffu, c1, o);
        }
        if (g == 0) {
            const int col0 = n0 + n_base + 8 * nt + 2 * tg;
            atomicAdd(&g_csum[z * 2048 + col0],     c0);
            atomicAdd(&g_csum[z * 2048 + col0 + 1], c1);
        }
    }
}

// ---------------------------------------------------------------------------
// out (merged): z<8 -> out_a = E @ ibt + resid_a ; z>=8 -> out_b = E^T @ iat + resid_b.
// ---------------------------------------------------------------------------
__global__ void __launch_bounds__(128, 2)
out_k(const float* __restrict__ ia, const float* __restrict__ ib,
      float* __restrict__ OUT)
{
    constexpr int NC = 2048 / BK;
    extern __shared__ __align__(16) char smem_raw[];
    const uint32_t smb = smem_u32(smem_raw);

    const int tid = threadIdx.x;
    const bool tra = blockIdx.z >= 8;
    const int z   = blockIdx.z & 7;
    const int m0  = blockIdx.y * BM;
    const int n0  = blockIdx.x * BN;

    const __half* Ah = g_s + (size_t)z * NLA * NLB;
    const __half* Bh = (tra ? g_iat : g_ibt) + (size_t)z * ND * 2048;
    const float* aux = (tra ? ib : ia) + (size_t)z * 2048 * ND;
    float* Cf = OUT + (tra ? (size_t)NB * NLA * ND : 0) + (size_t)z * 2048 * ND;

    // producer geometry
    const int r4 = tid >> 2;
    const int q4 = tid & 3;
    const uint32_t soff = (uint32_t)(r4 * ROWB + q4 * 16);
    const __half* gB = Bh + (size_t)(n0 + r4) * 2048 + q4 * 8;
    // trans-A: 32 rows x 256B, thread covers 64B of a row
    const uint32_t soffAT = (uint32_t)(r4 * APITCH_T + q4 * 64);
    const __half* gA_std = Ah + (size_t)(m0 + r4) * 2048 + q4 * 8;
    const __half* gA_tra = Ah + m0 + q4 * 32;

    auto issueChunk = [&](int c, int st) {
        const uint32_t sbase = smb + st * STG_B;
        if (tra) {
            const __half* ga = gA_tra + (size_t)(c * BK + r4) * 2048;
            #pragma unroll
            for (int q = 0; q < 4; ++q)
                cpa16(sbase + soffAT + q * 16, ga + q * 8);
        } else {
            #pragma unroll
            for (int p = 0; p < 4; ++p)
                cpa16(sbase + soff + p * (32 * ROWB),
                      gA_std + c * BK + (size_t)p * (32 * 2048));
        }
        #pragma unroll
        for (int p = 0; p < 4; ++p)
            cpa16(sbase + OPB_STD + soff + p * (32 * ROWB),
                  gB + c * BK + (size_t)p * (32 * 2048));
    };

    const int warp = tid >> 5, lane = tid & 31;
    const int wm = warp >> 1, wn = warp & 1;
    const int m_base = wm * 64, n_base = wn * 64;
    const int g = lane >> 2, tg = lane & 3;

    const uint32_t a_row = (uint32_t)(m_base + (lane & 15)) * ROWB + (lane >> 4) * 16;
    const uint32_t a_row_t = (uint32_t)((lane >> 4) * 8 + (lane & 7)) * APITCH_T
                           + ((lane >> 3) & 1) * 16 + (uint32_t)m_base * 2;
    const uint32_t b_row = (uint32_t)(n_base + ((lane >> 4) << 3) + (lane & 7)) * ROWB
                         + ((lane >> 3) & 1) * 16;

    float acc[4][8][4] = {};

    #pragma unroll
    for (int c = 0; c < 3; ++c) { issueChunk(c, c); cpa_commit(); }

    for (int c = 0; c < NC; ++c) {
        cpa_wait2();
        __syncthreads();
        const uint32_t ab = smb + (c & 3) * STG_B;
        const uint32_t bb2 = ab + OPB_STD;
        #pragma unroll
        for (int s = 0; s < 2; ++s) {
            uint32_t af[4][4], bq[4][4];
            if (tra) {
                #pragma unroll
                for (int mt = 0; mt < 4; ++mt)
                    ldm4t(af[mt], ab + a_row_t + 32 * mt + s * (16 * APITCH_T));
            } else {
                #pragma unroll
                for (int mt = 0; mt < 4; ++mt)
                    ldm4(af[mt], ab + a_row + mt * (16 * ROWB) + s * 32);
            }
            #pragma unroll
            for (int np = 0; np < 4; ++np)
                ldm4(bq[np], bb2 + b_row + np * (16 * ROWB) + s * 32);
            #pragma unroll
            for (int mt = 0; mt < 4; ++mt)
                #pragma unroll
                for (int nt = 0; nt < 8; ++nt)
                    mma_f16(acc[mt][nt],
                            af[mt][0], af[mt][1], af[mt][2], af[mt][3],
                            bq[nt >> 1][(nt & 1) * 2], bq[nt >> 1][(nt & 1) * 2 + 1]);
        }
        if (c + 3 < NC) issueChunk(c + 3, (c + 3) & 3);
        cpa_commit();
    }

    #pragma unroll
    for (int mt = 0; mt < 4; ++mt) {
        const int row0 = m0 + m_base + 16 * mt + g;
        #pragma unroll
        for (int nt = 0; nt < 8; ++nt) {
            const int col0 = n0 + n_base + 8 * nt + 2 * tg;
            const float2 e0 = *(const float2*)(aux + (size_t)row0 * 512 + col0);
            const float2 e1 = *(const float2*)(aux + (size_t)(row0 + 8) * 512 + col0);
            *(float2*)(Cf + (size_t)row0 * 512 + col0) =
                make_float2(acc[mt][nt][0] + e0.x, acc[mt][nt][1] + e0.y);
            *(float2*)(Cf + (size_t)(row0 + 8) * 512 + col0) =
                make_float2(acc[mt][nt][2] + e1.x, acc[mt][nt][3] + e1.y);
        }
    }
}

// ---------------------------------------------------------------------------
// prep_w: W (fp32) -> W^T fp16 (z: 0=Wa, 1=Wb); z==0 also zeroes sums.
// ---------------------------------------------------------------------------
__global__ void __launch_bounds__(256)
prep_w(const float* __restrict__ Wa, const float* __restrict__ Wb)
{
    __shared__ float tile[32][33];
    const int sel = blockIdx.z;
    const float* s = sel ? Wb : Wa;
    __half* d = sel ? g_wbt : g_wat;

    if (sel == 0) {
        const int lin = (blockIdx.y * gridDim.x + blockIdx.x) * 256
                      + threadIdx.y * 32 + threadIdx.x;
        if (lin < NB * 2048) { g_rsum[lin] = 0.f; g_csum[lin] = 0.f; }
    }

    int x = blockIdx.x * 32 + threadIdx.x;
    int y = blockIdx.y * 32 + threadIdx.y;
    #pragma unroll
    for (int j = 0; j < 32; j += 8)
        tile[threadIdx.y + j][threadIdx.x] = s[(size_t)(y + j) * 512 + x];
    __syncthreads();
    x = blockIdx.y * 32 + threadIdx.x;
    y = blockIdx.x * 32 + threadIdx.y;
    #pragma unroll
    for (int j = 0; j < 32; j += 8)
        d[(size_t)(y + j) * 512 + x] = __float2half(tile[threadIdx.x][threadIdx.y + j]);
}

// ---------------------------------------------------------------------------
// prep_io (merged a/b): fp32 input -> fp16 copy + fp16 transpose. z>=8 -> b.
// ---------------------------------------------------------------------------
__global__ void __launch_bounds__(256)
prep_io(const float* __restrict__ ia, const float* __restrict__ ib)
{
    __shared__ float tile[32][33];
    const bool sel = blockIdx.z >= 8;
    const int z = blockIdx.z & 7;
    const float* s = (sel ? ib : ia) + (size_t)z * 2048 * 512;
    __half* d = (sel ? g_ibt : g_iat) + (size_t)z * 2048 * 512;
    __half* c = (sel ? g_ihb : g_iha) + (size_t)z * 2048 * 512;

    int x = blockIdx.x * 32 + threadIdx.x;
    int y = blockIdx.y * 32 + threadIdx.y;
    #pragma unroll
    for (int j = 0; j < 32; j += 8) {
        float v = s[(size_t)(y + j) * 512 + x];
        tile[threadIdx.y + j][threadIdx.x] = v;
        c[(size_t)(y + j) * 512 + x] = __float2half(v);
    }
    __syncthreads();
    x = blockIdx.y * 32 + threadIdx.x;
    y = blockIdx.x * 32 + threadIdx.y;
    #pragma unroll
    for (int j = 0; j < 32; j += 8)
        d[(size_t)(y + j) * 2048 + x] = __float2half(tile[threadIdx.x][threadIdx.y + j]);
}

// ---------------------------------------------------------------------------
// scaleb (+fused recip): g_ibt *= 1/csum (y=0), g_iat *= 1/rsum (y=1).
// ---------------------------------------------------------------------------
__global__ void __launch_bounds__(256)
scaleb_k()
{
    const int idx = blockIdx.x * 256 + threadIdx.x;
    const int z = blockIdx.z;
    const int d = idx >> 8;
    const int j8 = (idx & 255) * 8;
    __half* base = (blockIdx.y ? g_iat : g_ibt) + (size_t)z * 512 * 2048 + (size_t)d * 2048 + j8;
    const float* sum = (blockIdx.y ? g_rsum : g_csum) + z * 2048 + j8;
    float inv[8];
    #pragma unroll
    for (int q = 0; q < 8; ++q) inv[q] = __frcp_rn(sum[q]);
    uint4 v = *(uint4*)base;
    __half2* hp = (__half2*)&v;
    #pragma unroll
    for (int q = 0; q < 4; ++q) {
        float2 f = __half22float2(hp[q]);
        f.x *= inv[2 * q];
        f.y *= inv[2 * q + 1];
        hp[q] = __floats2half2_rn(f.x, f.y);
    }
    *(uint4*)base = v;
}

// ---------------------------------------------------------------------------
extern "C" void kernel_launch(void* const* d_in, const int* in_sizes, int n_in,
                              void* d_out, int out_size)
{
    (void)in_sizes; (void)n_in; (void)out_size;
    const float* input_a = (const float*)d_in[0];
    const float* input_b = (const float*)d_in[1];
    const int*   mask_a  = (const int*)d_in[2];
    const int*   mask_b  = (const int*)d_in[3];
    const float* Wa      = (const float*)d_in[4];
    const float* ba      = (const float*)d_in[5];
    const float* Wb      = (const float*)d_in[6];
    const float* bb      = (const float*)d_in[7];
    float* out = (float*)d_out;

    static bool attr_done = false;
    if (!attr_done) {
        cudaFuncSetAttribute(proj_k,   cudaFuncAttributeMaxDynamicSharedMemorySize, DYN_SMEM);
        cudaFuncSetAttribute(scores_k, cudaFuncAttributeMaxDynamicSharedMemorySize, DYN_SMEM);
        cudaFuncSetAttribute(out_k,    cudaFuncAttributeMaxDynamicSharedMemorySize, DYN_SMEM);
        attr_done = true;
    }

    // prep: weight transposes (+sum zeroing), input copies+transposes
    prep_w <<<dim3(16, 16, 2),  dim3(32, 8)>>>(Wa, Wb);
    prep_io<<<dim3(16, 64, 16), dim3(32, 8)>>>(input_a, input_b);

    // projections (a+b merged) -> fp16 mapped
    proj_k<<<dim3(4, 128, 2), 128, DYN_SMEM>>>(ba, bb);

    // masked exp-scores -> g_s (fp16) + fused row/col sums
    scores_k<<<dim3(16, 16, NB), 128, DYN_SMEM>>>(mask_a, mask_b);

    // fold 1/sums into B operands
    scaleb_k<<<dim3(512, 2, NB), 256>>>();

    // attention-weighted outputs + residual (a+b merged)
    out_k<<<dim3(4, 16, 16), 128, DYN_SMEM>>>(input_a, input_b, out);
}